// round 1
// baseline (speedup 1.0000x reference)
#include <cuda_runtime.h>
#include <cuda_bf16.h>
#include <cstdint>

// Problem constants
#define Bx     4
#define Nn     1024
#define DIM    1024
#define HEADS  16
#define DH     64
#define INNER  1024
#define PROJ_H 16
#define TOP_K  256
#define SCALE  0.125f
#define LN_EPS 1e-5f

#define M_TOK  (Bx * Nn)          // 4096 tokens

// ---------------- scratch (device globals; no allocation allowed) -----------
__device__ float gQ[Bx * HEADS * Nn * DH];       // [B,H,N,DH]
__device__ float gK[Bx * HEADS * Nn * DH];
__device__ float gV[Bx * HEADS * Nn * DH];
__device__ float gScores[Bx * Nn];
__device__ float gGate[Bx * Nn];
__device__ float gAttnOut[Bx * Nn * INNER];      // [B,N,H*DH]

// ---------------- Kernel 1: QKV GEMM with scatter ---------------------------
// C[m,n] = sum_k X[m,k] * Wqkv[n,k]; M=4096, N=3072, K=1024
// 64x64 tile, BK=16, 256 threads, 4x4 per thread.
#define GBM 64
#define GBN 64
#define GBK 16

__global__ __launch_bounds__(256)
void qkv_gemm_kernel(const float* __restrict__ A, const float* __restrict__ Bm)
{
    __shared__ float As[GBK][GBM + 4];
    __shared__ float Bs[GBK][GBN + 4];

    const int tid = threadIdx.x;
    const int ty = tid >> 4;            // 0..15
    const int tx = tid & 15;            // 0..15
    const int m0 = blockIdx.y * GBM;
    const int n0 = blockIdx.x * GBN;

    const int lr = tid >> 2;            // 0..63 row in tile
    const int lc = (tid & 3) * 4;       // 0,4,8,12

    float acc[4][4];
#pragma unroll
    for (int i = 0; i < 4; i++)
#pragma unroll
        for (int j = 0; j < 4; j++) acc[i][j] = 0.f;

    for (int k0 = 0; k0 < DIM; k0 += GBK) {
        float4 av = *(const float4*)(A + (size_t)(m0 + lr) * DIM + k0 + lc);
        float4 bv = *(const float4*)(Bm + (size_t)(n0 + lr) * DIM + k0 + lc);
        As[lc + 0][lr] = av.x; As[lc + 1][lr] = av.y;
        As[lc + 2][lr] = av.z; As[lc + 3][lr] = av.w;
        Bs[lc + 0][lr] = bv.x; Bs[lc + 1][lr] = bv.y;
        Bs[lc + 2][lr] = bv.z; Bs[lc + 3][lr] = bv.w;
        __syncthreads();
#pragma unroll
        for (int kk = 0; kk < GBK; kk++) {
            float4 a = *(const float4*)&As[kk][ty * 4];
            float4 b = *(const float4*)&Bs[kk][tx * 4];
            float ar[4] = {a.x, a.y, a.z, a.w};
            float br[4] = {b.x, b.y, b.z, b.w};
#pragma unroll
            for (int i = 0; i < 4; i++)
#pragma unroll
                for (int j = 0; j < 4; j++) acc[i][j] += ar[i] * br[j];
        }
        __syncthreads();
    }

    // scatter to q/k/v [B,H,N,DH]
#pragma unroll
    for (int i = 0; i < 4; i++) {
        int m = m0 + ty * 4 + i;
        int b = m >> 10, irow = m & 1023;
#pragma unroll
        for (int j = 0; j < 4; j++) {
            int n = n0 + tx * 4 + j;
            int which = n >> 10;
            int inner = n & 1023;
            int h = inner >> 6, d = inner & 63;
            float* dst = (which == 0) ? gQ : (which == 1) ? gK : gV;
            dst[(((size_t)(b * HEADS + h)) * Nn + irow) * DH + d] = acc[i][j];
        }
    }
}

// ---------------- Kernel 2: gate scores (one 64-thread block per token) -----
__global__ __launch_bounds__(64)
void gate_scores_kernel(const float* __restrict__ ln_g, const float* __restrict__ ln_b,
                        const float* __restrict__ w1, const float* __restrict__ b1,
                        const float* __restrict__ w2, const float* __restrict__ b2)
{
    const int token = blockIdx.x;           // 0..4095
    const int b = token >> 10, n = token & 1023;
    const int d = threadIdx.x;              // 0..63

    float s = 0.f;
#pragma unroll
    for (int h = 0; h < HEADS; h++)
        s += gQ[(((size_t)(b * HEADS + h)) * Nn + n) * DH + d];
    const float qm = s * (1.0f / 16.0f);

    __shared__ float sh1[64], sh2[64], Hs[64], hp[16];
    sh1[d] = qm; sh2[d] = qm * qm;
    __syncthreads();
    for (int off = 32; off > 0; off >>= 1) {
        if (d < off) { sh1[d] += sh1[d + off]; sh2[d] += sh2[d + off]; }
        __syncthreads();
    }
    const float mu  = sh1[0] * (1.0f / 64.0f);
    const float var = sh2[0] * (1.0f / 64.0f) - mu * mu;
    const float Hd  = (qm - mu) * rsqrtf(var + LN_EPS) * ln_g[d] + ln_b[d];
    Hs[d] = Hd;
    __syncthreads();

    if (d < PROJ_H) {
        float a = b1[d];
#pragma unroll
        for (int e = 0; e < DH; e++) a += Hs[e] * w1[d * DH + e];
        hp[d] = 0.5f * a * (1.0f + erff(a * 0.70710678118654752f));   // exact gelu
    }
    __syncthreads();
    if (d == 0) {
        float sc = b2[0];
#pragma unroll
        for (int p = 0; p < PROJ_H; p++) sc += hp[p] * w2[p];
        gScores[token] = sc;   // TEMP = 1.0 -> divide is identity in fp32
    }
}

// ---------------- Kernel 3: per-batch top-k threshold + sigmoid gate --------
__global__ __launch_bounds__(256)
void topk_gate_kernel()
{
    const int b = blockIdx.x;
    const int tid = threadIdx.x;
    __shared__ float s[Nn];
    for (int t = tid; t < Nn; t += 256) s[t] = gScores[b * Nn + t];
    __syncthreads();

    // bitonic sort ascending
    for (int k = 2; k <= Nn; k <<= 1) {
        for (int j = k >> 1; j > 0; j >>= 1) {
            for (int t = tid; t < Nn; t += 256) {
                int ixj = t ^ j;
                if (ixj > t) {
                    float a = s[t], c = s[ixj];
                    bool asc = ((t & k) == 0);
                    if (asc ? (a > c) : (a < c)) { s[t] = c; s[ixj] = a; }
                }
            }
            __syncthreads();
        }
    }
    const float thresh = s[Nn - TOP_K];   // 256th largest
    for (int t = tid; t < Nn; t += 256) {
        float sc = gScores[b * Nn + t];
        gGate[b * Nn + t] = (sc >= thresh) ? (1.0f / (1.0f + expf(-sc))) : 0.0f;
    }
}

// ---------------- Kernel 4: gated attention ---------------------------------
// one thread per query row; j-tiles of 64 staged in smem; no-max softmax
// (|logit| <= ~4, exp cannot overflow; gated-out entries give exp(0)=1 exactly
//  matching the reference's zeroed logits).
#define AT_BI 128
#define AT_BJ 64

__global__ __launch_bounds__(128)
void attn_kernel()
{
    const int blk = blockIdx.x;            // 512 blocks
    const int it = blk & 7;                // i-tile (8 per bh)
    const int bh = blk >> 3;               // 0..63
    const int b = bh >> 4;
    const int h = bh & 15;
    const int i = it * AT_BI + threadIdx.x;
    const int tid = threadIdx.x;

    __shared__ float4 ksm[AT_BJ][16];
    __shared__ float4 vsm[AT_BJ][16];
    __shared__ float  gsm[AT_BJ];

    const float4* qp = (const float4*)(gQ + ((size_t)bh * Nn + i) * DH);
    float4 q[16];
#pragma unroll
    for (int c = 0; c < 16; c++) q[c] = qp[c];

    const float gi = gGate[b * Nn + i] * SCALE;

    float4 acc[16];
#pragma unroll
    for (int c = 0; c < 16; c++) acc[c] = make_float4(0.f, 0.f, 0.f, 0.f);
    float l = 0.f;

    for (int j0 = 0; j0 < Nn; j0 += AT_BJ) {
        __syncthreads();
        for (int t = tid; t < AT_BJ * 16; t += AT_BI) {
            int j = t >> 4, c = t & 15;
            ksm[j][c] = ((const float4*)(gK + ((size_t)bh * Nn + j0 + j) * DH))[c];
            vsm[j][c] = ((const float4*)(gV + ((size_t)bh * Nn + j0 + j) * DH))[c];
        }
        if (tid < AT_BJ) gsm[tid] = gGate[b * Nn + j0 + tid];
        __syncthreads();

#pragma unroll 2
        for (int j = 0; j < AT_BJ; j++) {
            float s = 0.f;
#pragma unroll
            for (int c = 0; c < 16; c++) {
                float4 kv = ksm[j][c];
                s += q[c].x * kv.x + q[c].y * kv.y + q[c].z * kv.z + q[c].w * kv.w;
            }
            float p = __expf(s * gi * gsm[j]);
            l += p;
#pragma unroll
            for (int c = 0; c < 16; c++) {
                float4 vv = vsm[j][c];
                acc[c].x += p * vv.x; acc[c].y += p * vv.y;
                acc[c].z += p * vv.z; acc[c].w += p * vv.w;
            }
        }
    }

    const float inv = 1.0f / l;
    float4* orow = (float4*)(gAttnOut + (((size_t)(b * Nn + i)) * HEADS + h) * DH);
#pragma unroll
    for (int c = 0; c < 16; c++) {
        float4 a = acc[c];
        a.x *= inv; a.y *= inv; a.z *= inv; a.w *= inv;
        orow[c] = a;
    }
}

// ---------------- Kernel 5: output projection + bias ------------------------
// out[m,n] = sum_k gAttnOut[m,k] * Wout[n,k] + b_out[n]; M=4096, N=1024, K=1024
__global__ __launch_bounds__(256)
void out_gemm_kernel(const float* __restrict__ Bm, const float* __restrict__ bias,
                     float* __restrict__ C)
{
    __shared__ float As[GBK][GBM + 4];
    __shared__ float Bs[GBK][GBN + 4];

    const int tid = threadIdx.x;
    const int ty = tid >> 4;
    const int tx = tid & 15;
    const int m0 = blockIdx.y * GBM;
    const int n0 = blockIdx.x * GBN;

    const int lr = tid >> 2;
    const int lc = (tid & 3) * 4;

    float acc[4][4];
#pragma unroll
    for (int i = 0; i < 4; i++)
#pragma unroll
        for (int j = 0; j < 4; j++) acc[i][j] = 0.f;

    for (int k0 = 0; k0 < INNER; k0 += GBK) {
        float4 av = *(const float4*)(gAttnOut + (size_t)(m0 + lr) * INNER + k0 + lc);
        float4 bv = *(const float4*)(Bm + (size_t)(n0 + lr) * INNER + k0 + lc);
        As[lc + 0][lr] = av.x; As[lc + 1][lr] = av.y;
        As[lc + 2][lr] = av.z; As[lc + 3][lr] = av.w;
        Bs[lc + 0][lr] = bv.x; Bs[lc + 1][lr] = bv.y;
        Bs[lc + 2][lr] = bv.z; Bs[lc + 3][lr] = bv.w;
        __syncthreads();
#pragma unroll
        for (int kk = 0; kk < GBK; kk++) {
            float4 a = *(const float4*)&As[kk][ty * 4];
            float4 b = *(const float4*)&Bs[kk][tx * 4];
            float ar[4] = {a.x, a.y, a.z, a.w};
            float br[4] = {b.x, b.y, b.z, b.w};
#pragma unroll
            for (int i = 0; i < 4; i++)
#pragma unroll
                for (int j = 0; j < 4; j++) acc[i][j] += ar[i] * br[j];
        }
        __syncthreads();
    }

#pragma unroll
    for (int i = 0; i < 4; i++) {
        int m = m0 + ty * 4 + i;
#pragma unroll
        for (int j = 0; j < 4; j++) {
            int n = n0 + tx * 4 + j;
            C[(size_t)m * DIM + n] = acc[i][j] + bias[n];
        }
    }
}

// ---------------- launch ----------------------------------------------------
extern "C" void kernel_launch(void* const* d_in, const int* in_sizes, int n_in,
                              void* d_out, int out_size)
{
    const float* x     = (const float*)d_in[0];
    const float* w_qkv = (const float*)d_in[1];
    const float* w_out = (const float*)d_in[2];
    const float* b_out = (const float*)d_in[3];
    const float* ln_g  = (const float*)d_in[4];
    const float* ln_b  = (const float*)d_in[5];
    const float* w1    = (const float*)d_in[6];
    const float* b1    = (const float*)d_in[7];
    const float* w2    = (const float*)d_in[8];
    const float* b2    = (const float*)d_in[9];
    float* out = (float*)d_out;

    // 1) QKV projection with head scatter
    qkv_gemm_kernel<<<dim3(3 * INNER / GBN, M_TOK / GBM), 256>>>(x, w_qkv);
    // 2) gate scores
    gate_scores_kernel<<<M_TOK, 64>>>(ln_g, ln_b, w1, b1, w2, b2);
    // 3) top-k mask + sigmoid
    topk_gate_kernel<<<Bx, 256>>>();
    // 4) gated attention
    attn_kernel<<<Bx * HEADS * (Nn / AT_BI), AT_BI>>>();
    // 5) output projection
    out_gemm_kernel<<<dim3(DIM / GBN, M_TOK / GBM), 256>>>(w_out, b_out, out);
}

// round 5
// speedup vs baseline: 2.4182x; 2.4182x over previous
#include <cuda_runtime.h>
#include <cuda_bf16.h>
#include <cstdint>

// Problem constants
#define Bx     4
#define Nn     1024
#define DIM    1024
#define HEADS  16
#define DH     64
#define INNER  1024
#define PROJ_H 16
#define TOP_K  256
#define SCALE  0.125f
#define LN_EPS 1e-5f

#define M_TOK  (Bx * Nn)          // 4096 tokens
#define BH     (Bx * HEADS)       // 64

// ---------------- scratch (device globals; no allocation allowed) -----------
__device__ float gQ[Bx * HEADS * Nn * DH];       // [B,H,N,DH]
__device__ float gK[Bx * HEADS * Nn * DH];
__device__ float gV[Bx * HEADS * Nn * DH];
__device__ float gScores[Bx * Nn];
__device__ float gGate[Bx * Nn];
__device__ float gAttnOut[Bx * Nn * INNER];      // [B,N,H*DH]

__device__ int   gActIdx[Bx * TOP_K];            // active token ids per batch
__device__ int   gActCount[Bx];
__device__ float gGateC[Bx * TOP_K];             // gate value per active token
__device__ float gKc[BH * TOP_K * DH];           // compact K [bh,jc,d]
__device__ float gVc[BH * TOP_K * DH];           // compact V
__device__ float gVsumAll[BH * DH];              // sum_j V[j]
__device__ float gVsumIn[BH * DH];               // sum_{gate_j==0} V[j]

// ---------------- Kernel 1: QKV GEMM with scatter (R1, known-good) ----------
#define GBM 64
#define GBN 64
#define GBK 16

__global__ __launch_bounds__(256)
void qkv_gemm_kernel(const float* __restrict__ A, const float* __restrict__ Bm)
{
    __shared__ float As[GBK][GBM + 4];
    __shared__ float Bs[GBK][GBN + 4];

    const int tid = threadIdx.x;
    const int ty = tid >> 4;
    const int tx = tid & 15;
    const int m0 = blockIdx.y * GBM;
    const int n0 = blockIdx.x * GBN;

    const int lr = tid >> 2;
    const int lc = (tid & 3) * 4;

    float acc[4][4];
#pragma unroll
    for (int i = 0; i < 4; i++)
#pragma unroll
        for (int j = 0; j < 4; j++) acc[i][j] = 0.f;

    for (int k0 = 0; k0 < DIM; k0 += GBK) {
        float4 av = *(const float4*)(A + (size_t)(m0 + lr) * DIM + k0 + lc);
        float4 bv = *(const float4*)(Bm + (size_t)(n0 + lr) * DIM + k0 + lc);
        As[lc + 0][lr] = av.x; As[lc + 1][lr] = av.y;
        As[lc + 2][lr] = av.z; As[lc + 3][lr] = av.w;
        Bs[lc + 0][lr] = bv.x; Bs[lc + 1][lr] = bv.y;
        Bs[lc + 2][lr] = bv.z; Bs[lc + 3][lr] = bv.w;
        __syncthreads();
#pragma unroll
        for (int kk = 0; kk < GBK; kk++) {
            float4 a = *(const float4*)&As[kk][ty * 4];
            float4 b = *(const float4*)&Bs[kk][tx * 4];
            float ar[4] = {a.x, a.y, a.z, a.w};
            float br[4] = {b.x, b.y, b.z, b.w};
#pragma unroll
            for (int i = 0; i < 4; i++)
#pragma unroll
                for (int j = 0; j < 4; j++) acc[i][j] += ar[i] * br[j];
        }
        __syncthreads();
    }

#pragma unroll
    for (int i = 0; i < 4; i++) {
        int m = m0 + ty * 4 + i;
        int b = m >> 10, irow = m & 1023;
#pragma unroll
        for (int j = 0; j < 4; j++) {
            int n = n0 + tx * 4 + j;
            int which = n >> 10;
            int inner = n & 1023;
            int h = inner >> 6, d = inner & 63;
            float* dst = (which == 0) ? gQ : (which == 1) ? gK : gV;
            dst[(((size_t)(b * HEADS + h)) * Nn + irow) * DH + d] = acc[i][j];
        }
    }
}

// ---------------- Kernel 2: gate scores -------------------------------------
__global__ __launch_bounds__(64)
void gate_scores_kernel(const float* __restrict__ ln_g, const float* __restrict__ ln_b,
                        const float* __restrict__ w1, const float* __restrict__ b1,
                        const float* __restrict__ w2, const float* __restrict__ b2)
{
    const int token = blockIdx.x;
    const int b = token >> 10, n = token & 1023;
    const int d = threadIdx.x;

    float s = 0.f;
#pragma unroll
    for (int h = 0; h < HEADS; h++)
        s += gQ[(((size_t)(b * HEADS + h)) * Nn + n) * DH + d];
    const float qm = s * (1.0f / 16.0f);

    __shared__ float sh1[64], sh2[64], Hs[64], hp[16];
    sh1[d] = qm; sh2[d] = qm * qm;
    __syncthreads();
    for (int off = 32; off > 0; off >>= 1) {
        if (d < off) { sh1[d] += sh1[d + off]; sh2[d] += sh2[d + off]; }
        __syncthreads();
    }
    const float mu  = sh1[0] * (1.0f / 64.0f);
    const float var = sh2[0] * (1.0f / 64.0f) - mu * mu;
    const float Hd  = (qm - mu) * rsqrtf(var + LN_EPS) * ln_g[d] + ln_b[d];
    Hs[d] = Hd;
    __syncthreads();

    if (d < PROJ_H) {
        float a = b1[d];
#pragma unroll
        for (int e = 0; e < DH; e++) a += Hs[e] * w1[d * DH + e];
        hp[d] = 0.5f * a * (1.0f + erff(a * 0.70710678118654752f));
    }
    __syncthreads();
    if (d == 0) {
        float sc = b2[0];
#pragma unroll
        for (int p = 0; p < PROJ_H; p++) sc += hp[p] * w2[p];
        gScores[token] = sc;
    }
}

// ---------------- Kernel 3: top-k threshold + sigmoid gate + active list ----
__global__ __launch_bounds__(256)
void topk_gate_kernel()
{
    const int b = blockIdx.x;
    const int tid = threadIdx.x;
    __shared__ float s[Nn];
    __shared__ int cnt;
    for (int t = tid; t < Nn; t += 256) s[t] = gScores[b * Nn + t];
    if (tid == 0) cnt = 0;
    __syncthreads();

    for (int k = 2; k <= Nn; k <<= 1) {
        for (int j = k >> 1; j > 0; j >>= 1) {
            for (int t = tid; t < Nn; t += 256) {
                int ixj = t ^ j;
                if (ixj > t) {
                    float a = s[t], c = s[ixj];
                    bool asc = ((t & k) == 0);
                    if (asc ? (a > c) : (a < c)) { s[t] = c; s[ixj] = a; }
                }
            }
            __syncthreads();
        }
    }
    const float thresh = s[Nn - TOP_K];
    for (int t = tid; t < Nn; t += 256) {
        float sc = gScores[b * Nn + t];
        float g = 0.0f;
        if (sc >= thresh) {
            int pos = atomicAdd(&cnt, 1);
            if (pos < TOP_K) {
                g = 1.0f / (1.0f + expf(-sc));
                gActIdx[b * TOP_K + pos] = t;
                gGateC[b * TOP_K + pos] = g;
            }
        }
        gGate[b * Nn + t] = g;
    }
    __syncthreads();
    if (tid == 0) gActCount[b] = (cnt < TOP_K) ? cnt : TOP_K;
}

// ---------------- Kernel 3b: compact K/V + V sums per (b,h) -----------------
__global__ __launch_bounds__(256)
void compact_kv_kernel()
{
    const int bh = blockIdx.x;            // 0..63
    const int b = bh >> 4;
    const int tid = threadIdx.x;
    const int jg = tid >> 6;              // 0..3
    const int d  = tid & 63;
    const int cnt = gActCount[b];

    // V sums
    float sAll = 0.f, sIn = 0.f;
    for (int j = jg; j < Nn; j += 4) {
        float v = gV[((size_t)bh * Nn + j) * DH + d];
        sAll += v;
        if (gGate[b * Nn + j] == 0.0f) sIn += v;
    }
    __shared__ float rA[4][64], rI[4][64];
    rA[jg][d] = sAll; rI[jg][d] = sIn;
    __syncthreads();
    if (jg == 0) {
        gVsumAll[bh * DH + d] = rA[0][d] + rA[1][d] + rA[2][d] + rA[3][d];
        gVsumIn[bh * DH + d]  = rI[0][d] + rI[1][d] + rI[2][d] + rI[3][d];
    }

    // gather compact K/V (float4 granularity: 16 per row)
    for (int idx = tid; idx < cnt * 16; idx += 256) {
        const int jc = idx >> 4, c = idx & 15;
        const int j = gActIdx[b * TOP_K + jc];
        const size_t src = ((size_t)bh * Nn + j) * 16 + c;     // float4 units
        const size_t dst = ((size_t)bh * TOP_K + jc) * 16 + c;
        ((float4*)gKc)[dst] = ((const float4*)gK)[src];
        ((float4*)gVc)[dst] = ((const float4*)gV)[src];
    }
}

// ---------------- Kernel 4a: attention for ACTIVE queries -------------------
// grid 128: blk -> (bh, half); thread = one active query.
#define AT_BJ 64

__global__ __launch_bounds__(128)
void attn_active_kernel()
{
    const int blk = blockIdx.x;
    const int bh = blk >> 1;
    const int half = blk & 1;
    const int b = bh >> 4;
    const int h = bh & 15;
    const int tid = threadIdx.x;
    const int ic = half * 128 + tid;

    const int cnt = gActCount[b];
    const bool live = (ic < cnt);
    const int i = live ? gActIdx[b * TOP_K + ic] : 0;

    __shared__ float4 ksm[AT_BJ][16];
    __shared__ float4 vsm[AT_BJ][16];
    __shared__ float  gsm[AT_BJ];

    float4 q[16];
    {
        const float4* qp = (const float4*)(gQ + ((size_t)bh * Nn + i) * DH);
#pragma unroll
        for (int c = 0; c < 16; c++) q[c] = qp[c];
    }
    const float gi = live ? gGate[b * Nn + i] * SCALE : 0.f;

    float4 acc[16];
    {
        const float4* vin = (const float4*)(gVsumIn + bh * DH);
#pragma unroll
        for (int c = 0; c < 16; c++) acc[c] = vin[c];
    }
    float l = (float)(Nn - cnt);

    for (int j0 = 0; j0 < cnt; j0 += AT_BJ) {
        const int jn = min(AT_BJ, cnt - j0);
        __syncthreads();
        for (int t = tid; t < AT_BJ * 16; t += 128) {
            int j = t >> 4, c = t & 15;
            if (j < jn) {
                const size_t src = ((size_t)bh * TOP_K + j0 + j) * 16 + c;
                ksm[j][c] = ((const float4*)gKc)[src];
                vsm[j][c] = ((const float4*)gVc)[src];
            }
        }
        if (tid < AT_BJ && tid < jn) gsm[tid] = gGateC[b * TOP_K + j0 + tid];
        __syncthreads();

        for (int j = 0; j < jn; j++) {
            float s = 0.f;
#pragma unroll
            for (int c = 0; c < 16; c++) {
                float4 kv = ksm[j][c];
                s += q[c].x * kv.x + q[c].y * kv.y + q[c].z * kv.z + q[c].w * kv.w;
            }
            float p = __expf(s * gi * gsm[j]);
            l += p;
#pragma unroll
            for (int c = 0; c < 16; c++) {
                float4 vv = vsm[j][c];
                acc[c].x += p * vv.x; acc[c].y += p * vv.y;
                acc[c].z += p * vv.z; acc[c].w += p * vv.w;
            }
        }
    }

    if (live) {
        const float inv = 1.0f / l;
        float4* orow = (float4*)(gAttnOut + (((size_t)(b * Nn + i)) * HEADS + h) * DH);
#pragma unroll
        for (int c = 0; c < 16; c++) {
            float4 a = acc[c];
            a.x *= inv; a.y *= inv; a.z *= inv; a.w *= inv;
            orow[c] = a;
        }
    }
}

// ---------------- Kernel 4b: attention for INACTIVE queries -----------------
// gate_i == 0  =>  all p = 1  =>  out = VsumAll / N
__global__ __launch_bounds__(64)
void attn_inactive_kernel()
{
    const int token = blockIdx.x;
    const int b = token >> 10, n = token & 1023;
    if (gGate[token] != 0.0f) return;
    const int d = threadIdx.x;
    const float invN = 1.0f / (float)Nn;
#pragma unroll
    for (int h = 0; h < HEADS; h++) {
        gAttnOut[(((size_t)(b * Nn + n)) * HEADS + h) * DH + d] =
            gVsumAll[(b * HEADS + h) * DH + d] * invN;
    }
}

// ---------------- Kernel 5: output projection + bias (R1, known-good) -------
__global__ __launch_bounds__(256)
void out_gemm_kernel(const float* __restrict__ Bm, const float* __restrict__ bias,
                     float* __restrict__ C)
{
    __shared__ float As[GBK][GBM + 4];
    __shared__ float Bs[GBK][GBN + 4];

    const int tid = threadIdx.x;
    const int ty = tid >> 4;
    const int tx = tid & 15;
    const int m0 = blockIdx.y * GBM;
    const int n0 = blockIdx.x * GBN;

    const int lr = tid >> 2;
    const int lc = (tid & 3) * 4;

    float acc[4][4];
#pragma unroll
    for (int i = 0; i < 4; i++)
#pragma unroll
        for (int j = 0; j < 4; j++) acc[i][j] = 0.f;

    for (int k0 = 0; k0 < INNER; k0 += GBK) {
        float4 av = *(const float4*)(gAttnOut + (size_t)(m0 + lr) * INNER + k0 + lc);
        float4 bv = *(const float4*)(Bm + (size_t)(n0 + lr) * INNER + k0 + lc);
        As[lc + 0][lr] = av.x; As[lc + 1][lr] = av.y;
        As[lc + 2][lr] = av.z; As[lc + 3][lr] = av.w;
        Bs[lc + 0][lr] = bv.x; Bs[lc + 1][lr] = bv.y;
        Bs[lc + 2][lr] = bv.z; Bs[lc + 3][lr] = bv.w;
        __syncthreads();
#pragma unroll
        for (int kk = 0; kk < GBK; kk++) {
            float4 a = *(const float4*)&As[kk][ty * 4];
            float4 b = *(const float4*)&Bs[kk][tx * 4];
            float ar[4] = {a.x, a.y, a.z, a.w};
            float br[4] = {b.x, b.y, b.z, b.w};
#pragma unroll
            for (int i = 0; i < 4; i++)
#pragma unroll
                for (int j = 0; j < 4; j++) acc[i][j] += ar[i] * br[j];
        }
        __syncthreads();
    }

#pragma unroll
    for (int i = 0; i < 4; i++) {
        int m = m0 + ty * 4 + i;
#pragma unroll
        for (int j = 0; j < 4; j++) {
            int n = n0 + tx * 4 + j;
            C[(size_t)m * DIM + n] = acc[i][j] + bias[n];
        }
    }
}

// ---------------- launch ----------------------------------------------------
extern "C" void kernel_launch(void* const* d_in, const int* in_sizes, int n_in,
                              void* d_out, int out_size)
{
    const float* x     = (const float*)d_in[0];
    const float* w_qkv = (const float*)d_in[1];
    const float* w_out = (const float*)d_in[2];
    const float* b_out = (const float*)d_in[3];
    const float* ln_g  = (const float*)d_in[4];
    const float* ln_b  = (const float*)d_in[5];
    const float* w1    = (const float*)d_in[6];
    const float* b1    = (const float*)d_in[7];
    const float* w2    = (const float*)d_in[8];
    const float* b2    = (const float*)d_in[9];
    float* out = (float*)d_out;

    qkv_gemm_kernel<<<dim3(3 * INNER / GBN, M_TOK / GBM), 256>>>(x, w_qkv);
    gate_scores_kernel<<<M_TOK, 64>>>(ln_g, ln_b, w1, b1, w2, b2);
    topk_gate_kernel<<<Bx, 256>>>();
    compact_kv_kernel<<<BH, 256>>>();
    attn_active_kernel<<<BH * 2, 128>>>();
    attn_inactive_kernel<<<M_TOK, 64>>>();
    out_gemm_kernel<<<dim3(DIM / GBN, M_TOK / GBM), 256>>>(w_out, b_out, out);
}

// round 7
// speedup vs baseline: 2.7422x; 1.1340x over previous
#include <cuda_runtime.h>
#include <cuda_bf16.h>
#include <cstdint>

// Problem constants
#define Bx     4
#define Nn     1024
#define DIM    1024
#define HEADS  16
#define DH     64
#define INNER  1024
#define PROJ_H 16
#define TOP_K  256
#define SCALE  0.125f
#define LN_EPS 1e-5f

#define M_TOK  (Bx * Nn)          // 4096 tokens
#define BH     (Bx * HEADS)       // 64

// ---------------- scratch (device globals; no allocation allowed) -----------
__device__ float gQ[Bx * HEADS * Nn * DH];       // [B,H,N,DH]
__device__ float gK[Bx * HEADS * Nn * DH];
__device__ float gV[Bx * HEADS * Nn * DH];
__device__ float gScores[Bx * Nn];
__device__ float gGate[Bx * Nn];
__device__ float gAttnOut[Bx * Nn * INNER];      // [B,N,H*DH] (active rows only)

__device__ int   gActIdx[Bx * TOP_K];
__device__ int   gActCount[Bx];
__device__ float gGateC[Bx * TOP_K];
__device__ float gKc[BH * TOP_K * DH];
__device__ float gVc[BH * TOP_K * DH];
__device__ float gVsumAll[BH * DH];
__device__ float gVsumIn[BH * DH];
__device__ float gInactRow[Bx * DIM];            // shared out-row per batch

// ---------------- Kernel 1: QKV GEMM with scatter (known-good) --------------
#define GBM 64
#define GBN 64
#define GBK 16

__global__ __launch_bounds__(256)
void qkv_gemm_kernel(const float* __restrict__ A, const float* __restrict__ Bm)
{
    __shared__ float As[GBK][GBM + 4];
    __shared__ float Bs[GBK][GBN + 4];

    const int tid = threadIdx.x;
    const int ty = tid >> 4;
    const int tx = tid & 15;
    const int m0 = blockIdx.y * GBM;
    const int n0 = blockIdx.x * GBN;

    const int lr = tid >> 2;
    const int lc = (tid & 3) * 4;

    float acc[4][4];
#pragma unroll
    for (int i = 0; i < 4; i++)
#pragma unroll
        for (int j = 0; j < 4; j++) acc[i][j] = 0.f;

    for (int k0 = 0; k0 < DIM; k0 += GBK) {
        float4 av = *(const float4*)(A + (size_t)(m0 + lr) * DIM + k0 + lc);
        float4 bv = *(const float4*)(Bm + (size_t)(n0 + lr) * DIM + k0 + lc);
        As[lc + 0][lr] = av.x; As[lc + 1][lr] = av.y;
        As[lc + 2][lr] = av.z; As[lc + 3][lr] = av.w;
        Bs[lc + 0][lr] = bv.x; Bs[lc + 1][lr] = bv.y;
        Bs[lc + 2][lr] = bv.z; Bs[lc + 3][lr] = bv.w;
        __syncthreads();
#pragma unroll
        for (int kk = 0; kk < GBK; kk++) {
            float4 a = *(const float4*)&As[kk][ty * 4];
            float4 b = *(const float4*)&Bs[kk][tx * 4];
            float ar[4] = {a.x, a.y, a.z, a.w};
            float br[4] = {b.x, b.y, b.z, b.w};
#pragma unroll
            for (int i = 0; i < 4; i++)
#pragma unroll
                for (int j = 0; j < 4; j++) acc[i][j] += ar[i] * br[j];
        }
        __syncthreads();
    }

#pragma unroll
    for (int i = 0; i < 4; i++) {
        int m = m0 + ty * 4 + i;
        int b = m >> 10, irow = m & 1023;
#pragma unroll
        for (int j = 0; j < 4; j++) {
            int n = n0 + tx * 4 + j;
            int which = n >> 10;
            int inner = n & 1023;
            int h = inner >> 6, d = inner & 63;
            float* dst = (which == 0) ? gQ : (which == 1) ? gK : gV;
            dst[(((size_t)(b * HEADS + h)) * Nn + irow) * DH + d] = acc[i][j];
        }
    }
}

// ---------------- Kernel 2: gate scores -------------------------------------
__global__ __launch_bounds__(64)
void gate_scores_kernel(const float* __restrict__ ln_g, const float* __restrict__ ln_b,
                        const float* __restrict__ w1, const float* __restrict__ b1,
                        const float* __restrict__ w2, const float* __restrict__ b2)
{
    const int token = blockIdx.x;
    const int b = token >> 10, n = token & 1023;
    const int d = threadIdx.x;

    float s = 0.f;
#pragma unroll
    for (int h = 0; h < HEADS; h++)
        s += gQ[(((size_t)(b * HEADS + h)) * Nn + n) * DH + d];
    const float qm = s * (1.0f / 16.0f);

    __shared__ float sh1[64], sh2[64], Hs[64], hp[16];
    sh1[d] = qm; sh2[d] = qm * qm;
    __syncthreads();
    for (int off = 32; off > 0; off >>= 1) {
        if (d < off) { sh1[d] += sh1[d + off]; sh2[d] += sh2[d + off]; }
        __syncthreads();
    }
    const float mu  = sh1[0] * (1.0f / 64.0f);
    const float var = sh2[0] * (1.0f / 64.0f) - mu * mu;
    const float Hd  = (qm - mu) * rsqrtf(var + LN_EPS) * ln_g[d] + ln_b[d];
    Hs[d] = Hd;
    __syncthreads();

    if (d < PROJ_H) {
        float a = b1[d];
#pragma unroll
        for (int e = 0; e < DH; e++) a += Hs[e] * w1[d * DH + e];
        hp[d] = 0.5f * a * (1.0f + erff(a * 0.70710678118654752f));
    }
    __syncthreads();
    if (d == 0) {
        float sc = b2[0];
#pragma unroll
        for (int p = 0; p < PROJ_H; p++) sc += hp[p] * w2[p];
        gScores[token] = sc;
    }
}

// ---------------- Kernel 3: top-k threshold + sigmoid gate + active list ----
__global__ __launch_bounds__(512)
void topk_gate_kernel()
{
    const int b = blockIdx.x;
    const int tid = threadIdx.x;
    __shared__ float s[Nn];
    __shared__ int cnt;
    for (int t = tid; t < Nn; t += 512) s[t] = gScores[b * Nn + t];
    if (tid == 0) cnt = 0;
    __syncthreads();

    for (int k = 2; k <= Nn; k <<= 1) {
        for (int j = k >> 1; j > 0; j >>= 1) {
            for (int t = tid; t < Nn; t += 512) {
                int ixj = t ^ j;
                if (ixj > t) {
                    float a = s[t], c = s[ixj];
                    bool asc = ((t & k) == 0);
                    if (asc ? (a > c) : (a < c)) { s[t] = c; s[ixj] = a; }
                }
            }
            __syncthreads();
        }
    }
    const float thresh = s[Nn - TOP_K];
    for (int t = tid; t < Nn; t += 512) {
        float sc = gScores[b * Nn + t];
        float g = 0.0f;
        if (sc >= thresh) {
            int pos = atomicAdd(&cnt, 1);
            if (pos < TOP_K) {
                g = 1.0f / (1.0f + expf(-sc));
                gActIdx[b * TOP_K + pos] = t;
                gGateC[b * TOP_K + pos] = g;
            }
        }
        gGate[b * Nn + t] = g;
    }
    __syncthreads();
    if (tid == 0) gActCount[b] = (cnt < TOP_K) ? cnt : TOP_K;
}

// ---------------- Kernel 3b: compact K/V + V sums per (b,h) -----------------
__global__ __launch_bounds__(256)
void compact_kv_kernel()
{
    const int bh = blockIdx.x;
    const int b = bh >> 4;
    const int tid = threadIdx.x;
    const int jg = tid >> 6;
    const int d  = tid & 63;
    const int cnt = gActCount[b];

    float sAll = 0.f, sIn = 0.f;
    for (int j = jg; j < Nn; j += 4) {
        float v = gV[((size_t)bh * Nn + j) * DH + d];
        sAll += v;
        if (gGate[b * Nn + j] == 0.0f) sIn += v;
    }
    __shared__ float rA[4][64], rI[4][64];
    rA[jg][d] = sAll; rI[jg][d] = sIn;
    __syncthreads();
    if (jg == 0) {
        gVsumAll[bh * DH + d] = rA[0][d] + rA[1][d] + rA[2][d] + rA[3][d];
        gVsumIn[bh * DH + d]  = rI[0][d] + rI[1][d] + rI[2][d] + rI[3][d];
    }

    for (int idx = tid; idx < cnt * 16; idx += 256) {
        const int jc = idx >> 4, c = idx & 15;
        const int j = gActIdx[b * TOP_K + jc];
        const size_t src = ((size_t)bh * Nn + j) * 16 + c;
        const size_t dst = ((size_t)bh * TOP_K + jc) * 16 + c;
        ((float4*)gKc)[dst] = ((const float4*)gK)[src];
        ((float4*)gVc)[dst] = ((const float4*)gV)[src];
    }
}

// ---------------- Kernel 4: attention for ACTIVE queries --------------------
#define AT_BJ 64

__global__ __launch_bounds__(128)
void attn_active_kernel()
{
    const int blk = blockIdx.x;
    const int bh = blk >> 1;
    const int half = blk & 1;
    const int b = bh >> 4;
    const int h = bh & 15;
    const int tid = threadIdx.x;
    const int ic = half * 128 + tid;

    const int cnt = gActCount[b];
    const bool live = (ic < cnt);
    const int i = live ? gActIdx[b * TOP_K + ic] : 0;

    __shared__ float4 ksm[AT_BJ][16];
    __shared__ float4 vsm[AT_BJ][16];
    __shared__ float  gsm[AT_BJ];

    float4 q[16];
    {
        const float4* qp = (const float4*)(gQ + ((size_t)bh * Nn + i) * DH);
#pragma unroll
        for (int c = 0; c < 16; c++) q[c] = qp[c];
    }
    const float gi = live ? gGate[b * Nn + i] * SCALE : 0.f;

    float4 acc[16];
    {
        const float4* vin = (const float4*)(gVsumIn + bh * DH);
#pragma unroll
        for (int c = 0; c < 16; c++) acc[c] = vin[c];
    }
    float l = (float)(Nn - cnt);

    for (int j0 = 0; j0 < cnt; j0 += AT_BJ) {
        const int jn = min(AT_BJ, cnt - j0);
        __syncthreads();
        for (int t = tid; t < AT_BJ * 16; t += 128) {
            int j = t >> 4, c = t & 15;
            if (j < jn) {
                const size_t src = ((size_t)bh * TOP_K + j0 + j) * 16 + c;
                ksm[j][c] = ((const float4*)gKc)[src];
                vsm[j][c] = ((const float4*)gVc)[src];
            }
        }
        if (tid < AT_BJ && tid < jn) gsm[tid] = gGateC[b * TOP_K + j0 + tid];
        __syncthreads();

        for (int j = 0; j < jn; j++) {
            float s = 0.f;
#pragma unroll
            for (int c = 0; c < 16; c++) {
                float4 kv = ksm[j][c];
                s += q[c].x * kv.x + q[c].y * kv.y + q[c].z * kv.z + q[c].w * kv.w;
            }
            float p = __expf(s * gi * gsm[j]);
            l += p;
#pragma unroll
            for (int c = 0; c < 16; c++) {
                float4 vv = vsm[j][c];
                acc[c].x += p * vv.x; acc[c].y += p * vv.y;
                acc[c].z += p * vv.z; acc[c].w += p * vv.w;
            }
        }
    }

    if (live) {
        const float inv = 1.0f / l;
        float4* orow = (float4*)(gAttnOut + (((size_t)(b * Nn + i)) * HEADS + h) * DH);
#pragma unroll
        for (int c = 0; c < 16; c++) {
            float4 a = acc[c];
            a.x *= inv; a.y *= inv; a.z *= inv; a.w *= inv;
            orow[c] = a;
        }
    }
}

// ---------------- Kernel 5a: output projection for ACTIVE rows --------------
// M = active tokens (4 batches x up to 256), gathered via gActIdx.
__global__ __launch_bounds__(256)
void out_gemm_active_kernel(const float* __restrict__ Bm, const float* __restrict__ bias,
                            float* __restrict__ C)
{
    __shared__ float As[GBK][GBM + 4];
    __shared__ float Bs[GBK][GBN + 4];
    __shared__ int   sidx[GBM];
    __shared__ int   slive[GBM];

    const int tid = threadIdx.x;
    const int ty = tid >> 4;
    const int tx = tid & 15;
    const int b  = blockIdx.y >> 2;        // batch
    const int mt = blockIdx.y & 3;         // 64-row tile within batch actives
    const int n0 = blockIdx.x * GBN;

    const int lr = tid >> 2;
    const int lc = (tid & 3) * 4;

    const int cnt = gActCount[b];
    if (tid < GBM) {
        const int ic = mt * GBM + tid;
        const bool lv = (ic < cnt);
        slive[tid] = lv;
        sidx[tid]  = lv ? gActIdx[b * TOP_K + ic] : gActIdx[b * TOP_K];
    }
    __syncthreads();

    const float* aptr = gAttnOut + ((size_t)(b * Nn + sidx[lr])) * INNER + lc;

    float acc[4][4];
#pragma unroll
    for (int i = 0; i < 4; i++)
#pragma unroll
        for (int j = 0; j < 4; j++) acc[i][j] = 0.f;

    for (int k0 = 0; k0 < INNER; k0 += GBK) {
        float4 av = *(const float4*)(aptr + k0);
        float4 bv = *(const float4*)(Bm + (size_t)(n0 + lr) * INNER + k0 + lc);
        As[lc + 0][lr] = av.x; As[lc + 1][lr] = av.y;
        As[lc + 2][lr] = av.z; As[lc + 3][lr] = av.w;
        Bs[lc + 0][lr] = bv.x; Bs[lc + 1][lr] = bv.y;
        Bs[lc + 2][lr] = bv.z; Bs[lc + 3][lr] = bv.w;
        __syncthreads();
#pragma unroll
        for (int kk = 0; kk < GBK; kk++) {
            float4 a = *(const float4*)&As[kk][ty * 4];
            float4 bb = *(const float4*)&Bs[kk][tx * 4];
            float ar[4] = {a.x, a.y, a.z, a.w};
            float br[4] = {bb.x, bb.y, bb.z, bb.w};
#pragma unroll
            for (int i = 0; i < 4; i++)
#pragma unroll
                for (int j = 0; j < 4; j++) acc[i][j] += ar[i] * br[j];
        }
        __syncthreads();
    }

#pragma unroll
    for (int i = 0; i < 4; i++) {
        const int r = ty * 4 + i;
        if (slive[r]) {
            const int token = sidx[r];
#pragma unroll
            for (int j = 0; j < 4; j++) {
                const int n = n0 + tx * 4 + j;
                C[((size_t)(b * Nn + token)) * DIM + n] = acc[i][j] + bias[n];
            }
        }
    }
}

// ---------------- Kernel 5b: shared out-row per batch (inactive tokens) -----
// rowOut_b[n] = sum_k (VsumAll_flat[b][k]/N) * Wout[n,k] + bias[n]
__global__ __launch_bounds__(256)
void inact_row_kernel(const float* __restrict__ Bm, const float* __restrict__ bias)
{
    const int b = blockIdx.y;
    const int n = blockIdx.x * 256 + threadIdx.x;
    const float invN = 1.0f / (float)Nn;

    const float4* vrow = (const float4*)(gVsumAll + b * INNER);  // [H*DH] flat
    const float4* wrow = (const float4*)(Bm + (size_t)n * INNER);
    float s = 0.f;
#pragma unroll 8
    for (int c = 0; c < INNER / 4; c++) {
        float4 v = vrow[c];
        float4 w = wrow[c];
        s += v.x * w.x + v.y * w.y + v.z * w.z + v.w * w.w;
    }
    gInactRow[b * DIM + n] = s * invN + bias[n];
}

// ---------------- Kernel 5c: broadcast shared row to inactive tokens --------
__global__ __launch_bounds__(256)
void inact_bcast_kernel(float* __restrict__ C)
{
    const int token = blockIdx.x;
    if (gGate[token] != 0.0f) return;
    const int b = token >> 10;
    const float4* src = (const float4*)(gInactRow + b * DIM);
    float4* dst = (float4*)(C + (size_t)token * DIM);
    for (int c = threadIdx.x; c < DIM / 4; c += 256) dst[c] = src[c];
}

// ---------------- launch ----------------------------------------------------
extern "C" void kernel_launch(void* const* d_in, const int* in_sizes, int n_in,
                              void* d_out, int out_size)
{
    const float* x     = (const float*)d_in[0];
    const float* w_qkv = (const float*)d_in[1];
    const float* w_out = (const float*)d_in[2];
    const float* b_out = (const float*)d_in[3];
    const float* ln_g  = (const float*)d_in[4];
    const float* ln_b  = (const float*)d_in[5];
    const float* w1    = (const float*)d_in[6];
    const float* b1    = (const float*)d_in[7];
    const float* w2    = (const float*)d_in[8];
    const float* b2    = (const float*)d_in[9];
    float* out = (float*)d_out;

    qkv_gemm_kernel<<<dim3(3 * INNER / GBN, M_TOK / GBM), 256>>>(x, w_qkv);
    gate_scores_kernel<<<M_TOK, 64>>>(ln_g, ln_b, w1, b1, w2, b2);
    topk_gate_kernel<<<Bx, 512>>>();
    compact_kv_kernel<<<BH, 256>>>();
    attn_active_kernel<<<BH * 2, 128>>>();
    out_gemm_active_kernel<<<dim3(DIM / GBN, Bx * 4), 256>>>(w_out, b_out, out);
    inact_row_kernel<<<dim3(DIM / 256, Bx), 256>>>(w_out, b_out);
    inact_bcast_kernel<<<M_TOK, 256>>>(out);
}

// round 8
// speedup vs baseline: 3.7699x; 1.3747x over previous
#include <cuda_runtime.h>
#include <cuda_bf16.h>
#include <cstdint>

// Problem constants
#define Bx     4
#define Nn     1024
#define DIM    1024
#define HEADS  16
#define DH     64
#define INNER  1024
#define PROJ_H 16
#define TOP_K  256
#define SCALE  0.125f
#define LN_EPS 1e-5f

#define M_TOK  (Bx * Nn)          // 4096 tokens
#define BH     (Bx * HEADS)       // 64

// ---------------- scratch (device globals; no allocation allowed) -----------
__device__ float gV[Bx * HEADS * Nn * DH];       // [B,H,N,DH] (all tokens)
__device__ float gWqm[DH * DIM];                 // (1/16) sum_h w_q rows
__device__ float gQmean[M_TOK * DH];             // token-mean q
__device__ float gScores[Bx * Nn];
__device__ float gGate[Bx * Nn];
__device__ float gAttnOut[Bx * Nn * INNER];      // active rows only

__device__ int   gActIdx[Bx * TOP_K];
__device__ int   gActCount[Bx];
__device__ float gGateC[Bx * TOP_K];
__device__ float gQc[BH * TOP_K * DH];           // compact Q (active only)
__device__ float gKc[BH * TOP_K * DH];           // compact K (active only)
__device__ float gVc[BH * TOP_K * DH];           // compact V (active only)
__device__ float gVsumAll[BH * DH];
__device__ float gVsumIn[BH * DH];
__device__ float gInactRow[Bx * DIM];

#define GBM 64
#define GBN 64
#define GBK 16

// ---------------- Kernel 0: fold head-mean into q weights -------------------
// gWqm[d, k] = (1/16) * sum_h w_qkv[h*64 + d, k]
__global__ __launch_bounds__(256)
void wqmean_kernel(const float* __restrict__ Wqkv)
{
    const int idx = blockIdx.x * 256 + threadIdx.x;     // 0..65535
    const int d = idx >> 10, k = idx & 1023;
    float s = 0.f;
#pragma unroll
    for (int h = 0; h < HEADS; h++)
        s += Wqkv[(size_t)(h * DH + d) * DIM + k];
    gWqm[(size_t)d * DIM + k] = s * (1.0f / 16.0f);
}

// ---------------- Kernel 0b: qmean GEMM (M=4096, N=64, K=1024) --------------
__global__ __launch_bounds__(256)
void qmean_gemm_kernel(const float* __restrict__ A)
{
    __shared__ float As[GBK][GBM + 4];
    __shared__ float Bs[GBK][GBN + 4];

    const int tid = threadIdx.x;
    const int ty = tid >> 4;
    const int tx = tid & 15;
    const int m0 = blockIdx.y * GBM;

    const int lr = tid >> 2;
    const int lc = (tid & 3) * 4;

    float acc[4][4];
#pragma unroll
    for (int i = 0; i < 4; i++)
#pragma unroll
        for (int j = 0; j < 4; j++) acc[i][j] = 0.f;

    for (int k0 = 0; k0 < DIM; k0 += GBK) {
        float4 av = *(const float4*)(A + (size_t)(m0 + lr) * DIM + k0 + lc);
        float4 bv = *(const float4*)(gWqm + (size_t)lr * DIM + k0 + lc);
        As[lc + 0][lr] = av.x; As[lc + 1][lr] = av.y;
        As[lc + 2][lr] = av.z; As[lc + 3][lr] = av.w;
        Bs[lc + 0][lr] = bv.x; Bs[lc + 1][lr] = bv.y;
        Bs[lc + 2][lr] = bv.z; Bs[lc + 3][lr] = bv.w;
        __syncthreads();
#pragma unroll
        for (int kk = 0; kk < GBK; kk++) {
            float4 a = *(const float4*)&As[kk][ty * 4];
            float4 b = *(const float4*)&Bs[kk][tx * 4];
            float ar[4] = {a.x, a.y, a.z, a.w};
            float br[4] = {b.x, b.y, b.z, b.w};
#pragma unroll
            for (int i = 0; i < 4; i++)
#pragma unroll
                for (int j = 0; j < 4; j++) acc[i][j] += ar[i] * br[j];
        }
        __syncthreads();
    }

#pragma unroll
    for (int i = 0; i < 4; i++) {
        const int m = m0 + ty * 4 + i;
#pragma unroll
        for (int j = 0; j < 4; j++)
            gQmean[(size_t)m * DH + tx * 4 + j] = acc[i][j];
    }
}

// ---------------- Kernel 1: gate scores (reads gQmean) ----------------------
__global__ __launch_bounds__(64)
void gate_scores_kernel(const float* __restrict__ ln_g, const float* __restrict__ ln_b,
                        const float* __restrict__ w1, const float* __restrict__ b1,
                        const float* __restrict__ w2, const float* __restrict__ b2)
{
    const int token = blockIdx.x;
    const int d = threadIdx.x;
    const float qm = gQmean[(size_t)token * DH + d];

    __shared__ float sh1[64], sh2[64], Hs[64], hp[16];
    sh1[d] = qm; sh2[d] = qm * qm;
    __syncthreads();
    for (int off = 32; off > 0; off >>= 1) {
        if (d < off) { sh1[d] += sh1[d + off]; sh2[d] += sh2[d + off]; }
        __syncthreads();
    }
    const float mu  = sh1[0] * (1.0f / 64.0f);
    const float var = sh2[0] * (1.0f / 64.0f) - mu * mu;
    const float Hd  = (qm - mu) * rsqrtf(var + LN_EPS) * ln_g[d] + ln_b[d];
    Hs[d] = Hd;
    __syncthreads();

    if (d < PROJ_H) {
        float a = b1[d];
#pragma unroll
        for (int e = 0; e < DH; e++) a += Hs[e] * w1[d * DH + e];
        hp[d] = 0.5f * a * (1.0f + erff(a * 0.70710678118654752f));
    }
    __syncthreads();
    if (d == 0) {
        float sc = b2[0];
#pragma unroll
        for (int p = 0; p < PROJ_H; p++) sc += hp[p] * w2[p];
        gScores[token] = sc;
    }
}

// ---------------- Kernel 2: top-k threshold + sigmoid gate + active list ----
__global__ __launch_bounds__(512)
void topk_gate_kernel()
{
    const int b = blockIdx.x;
    const int tid = threadIdx.x;
    __shared__ float s[Nn];
    __shared__ int cnt;
    for (int t = tid; t < Nn; t += 512) s[t] = gScores[b * Nn + t];
    if (tid == 0) cnt = 0;
    __syncthreads();

    for (int k = 2; k <= Nn; k <<= 1) {
        for (int j = k >> 1; j > 0; j >>= 1) {
            for (int t = tid; t < Nn; t += 512) {
                int ixj = t ^ j;
                if (ixj > t) {
                    float a = s[t], c = s[ixj];
                    bool asc = ((t & k) == 0);
                    if (asc ? (a > c) : (a < c)) { s[t] = c; s[ixj] = a; }
                }
            }
            __syncthreads();
        }
    }
    const float thresh = s[Nn - TOP_K];
    for (int t = tid; t < Nn; t += 512) {
        float sc = gScores[b * Nn + t];
        float g = 0.0f;
        if (sc >= thresh) {
            int pos = atomicAdd(&cnt, 1);
            if (pos < TOP_K) {
                g = 1.0f / (1.0f + expf(-sc));
                gActIdx[b * TOP_K + pos] = t;
                gGateC[b * TOP_K + pos] = g;
            }
        }
        gGate[b * Nn + t] = g;
    }
    __syncthreads();
    if (tid == 0) gActCount[b] = (cnt < TOP_K) ? cnt : TOP_K;
}

// ---------------- Kernel 3: V projection (all tokens) -----------------------
// C[m,n] = x[m,:] . w_v[n,:]  with w_v = w_qkv rows 2048..3071; scatter to gV
__global__ __launch_bounds__(256)
void v_gemm_kernel(const float* __restrict__ A, const float* __restrict__ Wv)
{
    __shared__ float As[GBK][GBM + 4];
    __shared__ float Bs[GBK][GBN + 4];

    const int tid = threadIdx.x;
    const int ty = tid >> 4;
    const int tx = tid & 15;
    const int m0 = blockIdx.y * GBM;
    const int n0 = blockIdx.x * GBN;

    const int lr = tid >> 2;
    const int lc = (tid & 3) * 4;

    float acc[4][4];
#pragma unroll
    for (int i = 0; i < 4; i++)
#pragma unroll
        for (int j = 0; j < 4; j++) acc[i][j] = 0.f;

    for (int k0 = 0; k0 < DIM; k0 += GBK) {
        float4 av = *(const float4*)(A + (size_t)(m0 + lr) * DIM + k0 + lc);
        float4 bv = *(const float4*)(Wv + (size_t)(n0 + lr) * DIM + k0 + lc);
        As[lc + 0][lr] = av.x; As[lc + 1][lr] = av.y;
        As[lc + 2][lr] = av.z; As[lc + 3][lr] = av.w;
        Bs[lc + 0][lr] = bv.x; Bs[lc + 1][lr] = bv.y;
        Bs[lc + 2][lr] = bv.z; Bs[lc + 3][lr] = bv.w;
        __syncthreads();
#pragma unroll
        for (int kk = 0; kk < GBK; kk++) {
            float4 a = *(const float4*)&As[kk][ty * 4];
            float4 b = *(const float4*)&Bs[kk][tx * 4];
            float ar[4] = {a.x, a.y, a.z, a.w};
            float br[4] = {b.x, b.y, b.z, b.w};
#pragma unroll
            for (int i = 0; i < 4; i++)
#pragma unroll
                for (int j = 0; j < 4; j++) acc[i][j] += ar[i] * br[j];
        }
        __syncthreads();
    }

#pragma unroll
    for (int i = 0; i < 4; i++) {
        const int m = m0 + ty * 4 + i;
        const int b = m >> 10, irow = m & 1023;
#pragma unroll
        for (int j = 0; j < 4; j++) {
            const int n = n0 + tx * 4 + j;
            const int h = n >> 6, d = n & 63;
            gV[(((size_t)(b * HEADS + h)) * Nn + irow) * DH + d] = acc[i][j];
        }
    }
}

// ---------------- Kernel 4: QK projection for ACTIVE tokens only ------------
// M rows gathered via gActIdx; N=2048 (q then k); writes compact gQc/gKc.
__global__ __launch_bounds__(256)
void qk_active_gemm_kernel(const float* __restrict__ A, const float* __restrict__ Wqkv)
{
    __shared__ float As[GBK][GBM + 4];
    __shared__ float Bs[GBK][GBN + 4];
    __shared__ int   sidx[GBM];
    __shared__ int   slive[GBM];

    const int tid = threadIdx.x;
    const int ty = tid >> 4;
    const int tx = tid & 15;
    const int b  = blockIdx.y >> 2;
    const int mt = blockIdx.y & 3;
    const int n0 = blockIdx.x * GBN;       // 0..2047

    const int lr = tid >> 2;
    const int lc = (tid & 3) * 4;

    const int cnt = gActCount[b];
    if (tid < GBM) {
        const int ic = mt * GBM + tid;
        const bool lv = (ic < cnt);
        slive[tid] = lv;
        sidx[tid]  = lv ? gActIdx[b * TOP_K + ic] : gActIdx[b * TOP_K];
    }
    __syncthreads();

    const float* aptr = A + ((size_t)(b * Nn + sidx[lr])) * DIM + lc;

    float acc[4][4];
#pragma unroll
    for (int i = 0; i < 4; i++)
#pragma unroll
        for (int j = 0; j < 4; j++) acc[i][j] = 0.f;

    for (int k0 = 0; k0 < DIM; k0 += GBK) {
        float4 av = *(const float4*)(aptr + k0);
        float4 bv = *(const float4*)(Wqkv + (size_t)(n0 + lr) * DIM + k0 + lc);
        As[lc + 0][lr] = av.x; As[lc + 1][lr] = av.y;
        As[lc + 2][lr] = av.z; As[lc + 3][lr] = av.w;
        Bs[lc + 0][lr] = bv.x; Bs[lc + 1][lr] = bv.y;
        Bs[lc + 2][lr] = bv.z; Bs[lc + 3][lr] = bv.w;
        __syncthreads();
#pragma unroll
        for (int kk = 0; kk < GBK; kk++) {
            float4 a = *(const float4*)&As[kk][ty * 4];
            float4 bb = *(const float4*)&Bs[kk][tx * 4];
            float ar[4] = {a.x, a.y, a.z, a.w};
            float br[4] = {bb.x, bb.y, bb.z, bb.w};
#pragma unroll
            for (int i = 0; i < 4; i++)
#pragma unroll
                for (int j = 0; j < 4; j++) acc[i][j] += ar[i] * br[j];
        }
        __syncthreads();
    }

#pragma unroll
    for (int i = 0; i < 4; i++) {
        const int r = ty * 4 + i;
        if (slive[r]) {
            const int ic = mt * GBM + r;
#pragma unroll
            for (int j = 0; j < 4; j++) {
                const int n = n0 + tx * 4 + j;
                const int which = n >> 10;          // 0=q, 1=k
                const int inner = n & 1023;
                const int h = inner >> 6, d = inner & 63;
                float* dst = which ? gKc : gQc;
                dst[(((size_t)(b * HEADS + h)) * TOP_K + ic) * DH + d] = acc[i][j];
            }
        }
    }
}

// ---------------- Kernel 5: V sums + V compact gather per (b,h) -------------
__global__ __launch_bounds__(256)
void compact_v_kernel()
{
    const int bh = blockIdx.x;
    const int b = bh >> 4;
    const int tid = threadIdx.x;
    const int jg = tid >> 6;
    const int d  = tid & 63;
    const int cnt = gActCount[b];

    float sAll = 0.f, sIn = 0.f;
    for (int j = jg; j < Nn; j += 4) {
        float v = gV[((size_t)bh * Nn + j) * DH + d];
        sAll += v;
        if (gGate[b * Nn + j] == 0.0f) sIn += v;
    }
    __shared__ float rA[4][64], rI[4][64];
    rA[jg][d] = sAll; rI[jg][d] = sIn;
    __syncthreads();
    if (jg == 0) {
        gVsumAll[bh * DH + d] = rA[0][d] + rA[1][d] + rA[2][d] + rA[3][d];
        gVsumIn[bh * DH + d]  = rI[0][d] + rI[1][d] + rI[2][d] + rI[3][d];
    }

    for (int idx = tid; idx < cnt * 16; idx += 256) {
        const int jc = idx >> 4, c = idx & 15;
        const int j = gActIdx[b * TOP_K + jc];
        ((float4*)gVc)[((size_t)bh * TOP_K + jc) * 16 + c] =
            ((const float4*)gV)[((size_t)bh * Nn + j) * 16 + c];
    }
}

// ---------------- Kernel 6: attention for ACTIVE queries --------------------
#define AT_BJ 64

__global__ __launch_bounds__(128)
void attn_active_kernel()
{
    const int blk = blockIdx.x;
    const int bh = blk >> 1;
    const int half = blk & 1;
    const int b = bh >> 4;
    const int h = bh & 15;
    const int tid = threadIdx.x;
    const int ic = half * 128 + tid;

    const int cnt = gActCount[b];
    const bool live = (ic < cnt);
    const int i = live ? gActIdx[b * TOP_K + ic] : 0;

    __shared__ float4 ksm[AT_BJ][16];
    __shared__ float4 vsm[AT_BJ][16];
    __shared__ float  gsm[AT_BJ];

    float4 q[16];
    {
        const float4* qp = (const float4*)(gQc + ((size_t)bh * TOP_K + ic) * DH);
#pragma unroll
        for (int c = 0; c < 16; c++) q[c] = live ? qp[c] : make_float4(0.f, 0.f, 0.f, 0.f);
    }
    const float gi = live ? gGateC[b * TOP_K + ic] * SCALE : 0.f;

    float4 acc[16];
    {
        const float4* vin = (const float4*)(gVsumIn + bh * DH);
#pragma unroll
        for (int c = 0; c < 16; c++) acc[c] = vin[c];
    }
    float l = (float)(Nn - cnt);

    for (int j0 = 0; j0 < cnt; j0 += AT_BJ) {
        const int jn = min(AT_BJ, cnt - j0);
        __syncthreads();
        for (int t = tid; t < AT_BJ * 16; t += 128) {
            int j = t >> 4, c = t & 15;
            if (j < jn) {
                const size_t src = ((size_t)bh * TOP_K + j0 + j) * 16 + c;
                ksm[j][c] = ((const float4*)gKc)[src];
                vsm[j][c] = ((const float4*)gVc)[src];
            }
        }
        if (tid < AT_BJ && tid < jn) gsm[tid] = gGateC[b * TOP_K + j0 + tid];
        __syncthreads();

        for (int j = 0; j < jn; j++) {
            float s = 0.f;
#pragma unroll
            for (int c = 0; c < 16; c++) {
                float4 kv = ksm[j][c];
                s += q[c].x * kv.x + q[c].y * kv.y + q[c].z * kv.z + q[c].w * kv.w;
            }
            float p = __expf(s * gi * gsm[j]);
            l += p;
#pragma unroll
            for (int c = 0; c < 16; c++) {
                float4 vv = vsm[j][c];
                acc[c].x += p * vv.x; acc[c].y += p * vv.y;
                acc[c].z += p * vv.z; acc[c].w += p * vv.w;
            }
        }
    }

    if (live) {
        const float inv = 1.0f / l;
        float4* orow = (float4*)(gAttnOut + (((size_t)(b * Nn + i)) * HEADS + h) * DH);
#pragma unroll
        for (int c = 0; c < 16; c++) {
            float4 a = acc[c];
            a.x *= inv; a.y *= inv; a.z *= inv; a.w *= inv;
            orow[c] = a;
        }
    }
}

// ---------------- Kernel 7a: output projection for ACTIVE rows --------------
__global__ __launch_bounds__(256)
void out_gemm_active_kernel(const float* __restrict__ Bm, const float* __restrict__ bias,
                            float* __restrict__ C)
{
    __shared__ float As[GBK][GBM + 4];
    __shared__ float Bs[GBK][GBN + 4];
    __shared__ int   sidx[GBM];
    __shared__ int   slive[GBM];

    const int tid = threadIdx.x;
    const int ty = tid >> 4;
    const int tx = tid & 15;
    const int b  = blockIdx.y >> 2;
    const int mt = blockIdx.y & 3;
    const int n0 = blockIdx.x * GBN;

    const int lr = tid >> 2;
    const int lc = (tid & 3) * 4;

    const int cnt = gActCount[b];
    if (tid < GBM) {
        const int ic = mt * GBM + tid;
        const bool lv = (ic < cnt);
        slive[tid] = lv;
        sidx[tid]  = lv ? gActIdx[b * TOP_K + ic] : gActIdx[b * TOP_K];
    }
    __syncthreads();

    const float* aptr = gAttnOut + ((size_t)(b * Nn + sidx[lr])) * INNER + lc;

    float acc[4][4];
#pragma unroll
    for (int i = 0; i < 4; i++)
#pragma unroll
        for (int j = 0; j < 4; j++) acc[i][j] = 0.f;

    for (int k0 = 0; k0 < INNER; k0 += GBK) {
        float4 av = *(const float4*)(aptr + k0);
        float4 bv = *(const float4*)(Bm + (size_t)(n0 + lr) * INNER + k0 + lc);
        As[lc + 0][lr] = av.x; As[lc + 1][lr] = av.y;
        As[lc + 2][lr] = av.z; As[lc + 3][lr] = av.w;
        Bs[lc + 0][lr] = bv.x; Bs[lc + 1][lr] = bv.y;
        Bs[lc + 2][lr] = bv.z; Bs[lc + 3][lr] = bv.w;
        __syncthreads();
#pragma unroll
        for (int kk = 0; kk < GBK; kk++) {
            float4 a = *(const float4*)&As[kk][ty * 4];
            float4 bb = *(const float4*)&Bs[kk][tx * 4];
            float ar[4] = {a.x, a.y, a.z, a.w};
            float br[4] = {bb.x, bb.y, bb.z, bb.w};
#pragma unroll
            for (int i = 0; i < 4; i++)
#pragma unroll
                for (int j = 0; j < 4; j++) acc[i][j] += ar[i] * br[j];
        }
        __syncthreads();
    }

#pragma unroll
    for (int i = 0; i < 4; i++) {
        const int r = ty * 4 + i;
        if (slive[r]) {
            const int token = sidx[r];
#pragma unroll
            for (int j = 0; j < 4; j++) {
                const int n = n0 + tx * 4 + j;
                C[((size_t)(b * Nn + token)) * DIM + n] = acc[i][j] + bias[n];
            }
        }
    }
}

// ---------------- Kernel 7b: shared out-row per batch -----------------------
__global__ __launch_bounds__(256)
void inact_row_kernel(const float* __restrict__ Bm, const float* __restrict__ bias)
{
    const int b = blockIdx.y;
    const int n = blockIdx.x * 256 + threadIdx.x;
    const float invN = 1.0f / (float)Nn;

    const float4* vrow = (const float4*)(gVsumAll + b * INNER);
    const float4* wrow = (const float4*)(Bm + (size_t)n * INNER);
    float s = 0.f;
#pragma unroll 8
    for (int c = 0; c < INNER / 4; c++) {
        float4 v = vrow[c];
        float4 w = wrow[c];
        s += v.x * w.x + v.y * w.y + v.z * w.z + v.w * w.w;
    }
    gInactRow[b * DIM + n] = s * invN + bias[n];
}

// ---------------- Kernel 7c: broadcast shared row to inactive tokens --------
__global__ __launch_bounds__(256)
void inact_bcast_kernel(float* __restrict__ C)
{
    const int token = blockIdx.x;
    if (gGate[token] != 0.0f) return;
    const int b = token >> 10;
    const float4* src = (const float4*)(gInactRow + b * DIM);
    float4* dst = (float4*)(C + (size_t)token * DIM);
    for (int c = threadIdx.x; c < DIM / 4; c += 256) dst[c] = src[c];
}

// ---------------- launch ----------------------------------------------------
extern "C" void kernel_launch(void* const* d_in, const int* in_sizes, int n_in,
                              void* d_out, int out_size)
{
    const float* x     = (const float*)d_in[0];
    const float* w_qkv = (const float*)d_in[1];
    const float* w_out = (const float*)d_in[2];
    const float* b_out = (const float*)d_in[3];
    const float* ln_g  = (const float*)d_in[4];
    const float* ln_b  = (const float*)d_in[5];
    const float* w1    = (const float*)d_in[6];
    const float* b1    = (const float*)d_in[7];
    const float* w2    = (const float*)d_in[8];
    const float* b2    = (const float*)d_in[9];
    float* out = (float*)d_out;

    // gate-first pipeline
    wqmean_kernel<<<DH * DIM / 256, 256>>>(w_qkv);
    qmean_gemm_kernel<<<dim3(1, M_TOK / GBM), 256>>>(x);
    gate_scores_kernel<<<M_TOK, 64>>>(ln_g, ln_b, w1, b1, w2, b2);
    topk_gate_kernel<<<Bx, 512>>>();

    // projections (V full; QK active-only, straight into compact layout)
    v_gemm_kernel<<<dim3(INNER / GBN, M_TOK / GBM), 256>>>(x, w_qkv + 2 * (size_t)INNER * DIM);
    qk_active_gemm_kernel<<<dim3(2 * INNER / GBN, Bx * 4), 256>>>(x, w_qkv);
    compact_v_kernel<<<BH, 256>>>();

    // attention + output
    attn_active_kernel<<<BH * 2, 128>>>();
    out_gemm_active_kernel<<<dim3(DIM / GBN, Bx * 4), 256>>>(w_out, b_out, out);
    inact_row_kernel<<<dim3(DIM / 256, Bx), 256>>>(w_out, b_out);
    inact_bcast_kernel<<<M_TOK, 256>>>(out);
}

// round 9
// speedup vs baseline: 4.9330x; 1.3085x over previous
#include <cuda_runtime.h>
#include <cuda_bf16.h>
#include <cstdint>

// Problem constants
#define Bx     4
#define Nn     1024
#define DIM    1024
#define HEADS  16
#define DH     64
#define INNER  1024
#define PROJ_H 16
#define TOP_K  256
#define SCALE  0.125f
#define LN_EPS 1e-5f

#define M_TOK  (Bx * Nn)          // 4096 tokens
#define BH     (Bx * HEADS)       // 64

// ---------------- scratch (device globals; no allocation allowed) -----------
__device__ float gWqm[DH * DIM];                 // (1/16) sum_h w_q rows
__device__ float gQmean[M_TOK * DH];
__device__ float gScores[Bx * Nn];
__device__ float gGate[Bx * Nn];
__device__ float gAttnOut[Bx * Nn * INNER];      // active rows only

__device__ int   gActIdx[Bx * TOP_K];
__device__ int   gActCount[Bx];
__device__ float gGateC[Bx * TOP_K];
__device__ float gQc[BH * TOP_K * DH];           // compact Q (active only)
__device__ float gKc[BH * TOP_K * DH];           // compact K
__device__ float gVc[BH * TOP_K * DH];           // compact V
__device__ float gXsumP[8 * Bx * DIM];           // partial x sums
__device__ float gXsum[Bx * DIM];                // per-batch sum of x rows
__device__ float gVsumAll[BH * DH];              // = Wv . xsum
__device__ float gVsumIn[BH * DH];               // = VsumAll - sum(active V)
__device__ float gInactRow[Bx * DIM];

#define GBM 64
#define GBN 64
#define GBK 16

// ---------------- Kernel 0: fold head-mean into q weights -------------------
__global__ __launch_bounds__(256)
void wqmean_kernel(const float* __restrict__ Wqkv)
{
    const int idx = blockIdx.x * 256 + threadIdx.x;
    const int d = idx >> 10, k = idx & 1023;
    float s = 0.f;
#pragma unroll
    for (int h = 0; h < HEADS; h++)
        s += Wqkv[(size_t)(h * DH + d) * DIM + k];
    gWqm[(size_t)d * DIM + k] = s * (1.0f / 16.0f);
}

// ---------------- Kernel 0b: qmean GEMM (M=4096, N=64, K=1024) --------------
__global__ __launch_bounds__(256)
void qmean_gemm_kernel(const float* __restrict__ A)
{
    __shared__ float As[GBK][GBM + 4];
    __shared__ float Bs[GBK][GBN + 4];

    const int tid = threadIdx.x;
    const int ty = tid >> 4;
    const int tx = tid & 15;
    const int m0 = blockIdx.y * GBM;

    const int lr = tid >> 2;
    const int lc = (tid & 3) * 4;

    float acc[4][4];
#pragma unroll
    for (int i = 0; i < 4; i++)
#pragma unroll
        for (int j = 0; j < 4; j++) acc[i][j] = 0.f;

    for (int k0 = 0; k0 < DIM; k0 += GBK) {
        float4 av = *(const float4*)(A + (size_t)(m0 + lr) * DIM + k0 + lc);
        float4 bv = *(const float4*)(gWqm + (size_t)lr * DIM + k0 + lc);
        As[lc + 0][lr] = av.x; As[lc + 1][lr] = av.y;
        As[lc + 2][lr] = av.z; As[lc + 3][lr] = av.w;
        Bs[lc + 0][lr] = bv.x; Bs[lc + 1][lr] = bv.y;
        Bs[lc + 2][lr] = bv.z; Bs[lc + 3][lr] = bv.w;
        __syncthreads();
#pragma unroll
        for (int kk = 0; kk < GBK; kk++) {
            float4 a = *(const float4*)&As[kk][ty * 4];
            float4 b = *(const float4*)&Bs[kk][tx * 4];
            float ar[4] = {a.x, a.y, a.z, a.w};
            float br[4] = {b.x, b.y, b.z, b.w};
#pragma unroll
            for (int i = 0; i < 4; i++)
#pragma unroll
                for (int j = 0; j < 4; j++) acc[i][j] += ar[i] * br[j];
        }
        __syncthreads();
    }

#pragma unroll
    for (int i = 0; i < 4; i++) {
        const int m = m0 + ty * 4 + i;
#pragma unroll
        for (int j = 0; j < 4; j++)
            gQmean[(size_t)m * DH + tx * 4 + j] = acc[i][j];
    }
}

// ---------------- Kernel 1: gate scores -------------------------------------
__global__ __launch_bounds__(64)
void gate_scores_kernel(const float* __restrict__ ln_g, const float* __restrict__ ln_b,
                        const float* __restrict__ w1, const float* __restrict__ b1,
                        const float* __restrict__ w2, const float* __restrict__ b2)
{
    const int token = blockIdx.x;
    const int d = threadIdx.x;
    const float qm = gQmean[(size_t)token * DH + d];

    __shared__ float sh1[64], sh2[64], Hs[64], hp[16];
    sh1[d] = qm; sh2[d] = qm * qm;
    __syncthreads();
    for (int off = 32; off > 0; off >>= 1) {
        if (d < off) { sh1[d] += sh1[d + off]; sh2[d] += sh2[d + off]; }
        __syncthreads();
    }
    const float mu  = sh1[0] * (1.0f / 64.0f);
    const float var = sh2[0] * (1.0f / 64.0f) - mu * mu;
    const float Hd  = (qm - mu) * rsqrtf(var + LN_EPS) * ln_g[d] + ln_b[d];
    Hs[d] = Hd;
    __syncthreads();

    if (d < PROJ_H) {
        float a = b1[d];
#pragma unroll
        for (int e = 0; e < DH; e++) a += Hs[e] * w1[d * DH + e];
        hp[d] = 0.5f * a * (1.0f + erff(a * 0.70710678118654752f));
    }
    __syncthreads();
    if (d == 0) {
        float sc = b2[0];
#pragma unroll
        for (int p = 0; p < PROJ_H; p++) sc += hp[p] * w2[p];
        gScores[token] = sc;
    }
}

// ---------------- Kernel 2: top-k threshold + sigmoid gate + active list ----
__global__ __launch_bounds__(512)
void topk_gate_kernel()
{
    const int b = blockIdx.x;
    const int tid = threadIdx.x;
    __shared__ float s[Nn];
    __shared__ int cnt;
    for (int t = tid; t < Nn; t += 512) s[t] = gScores[b * Nn + t];
    if (tid == 0) cnt = 0;
    __syncthreads();

    for (int k = 2; k <= Nn; k <<= 1) {
        for (int j = k >> 1; j > 0; j >>= 1) {
            for (int t = tid; t < Nn; t += 512) {
                int ixj = t ^ j;
                if (ixj > t) {
                    float a = s[t], c = s[ixj];
                    bool asc = ((t & k) == 0);
                    if (asc ? (a > c) : (a < c)) { s[t] = c; s[ixj] = a; }
                }
            }
            __syncthreads();
        }
    }
    const float thresh = s[Nn - TOP_K];
    for (int t = tid; t < Nn; t += 512) {
        float sc = gScores[b * Nn + t];
        float g = 0.0f;
        if (sc >= thresh) {
            int pos = atomicAdd(&cnt, 1);
            if (pos < TOP_K) {
                g = 1.0f / (1.0f + expf(-sc));
                gActIdx[b * TOP_K + pos] = t;
                gGateC[b * TOP_K + pos] = g;
            }
        }
        gGate[b * Nn + t] = g;
    }
    __syncthreads();
    if (tid == 0) gActCount[b] = (cnt < TOP_K) ? cnt : TOP_K;
}

// ---------------- Kernel 3: QKV projection for ACTIVE tokens ----------------
// M rows gathered via gActIdx; N=3072 (q,k,v); writes compact gQc/gKc/gVc.
__global__ __launch_bounds__(256)
void qkv_active_gemm_kernel(const float* __restrict__ A, const float* __restrict__ Wqkv)
{
    __shared__ float As[GBK][GBM + 4];
    __shared__ float Bs[GBK][GBN + 4];
    __shared__ int   sidx[GBM];
    __shared__ int   slive[GBM];

    const int tid = threadIdx.x;
    const int ty = tid >> 4;
    const int tx = tid & 15;
    const int b  = blockIdx.y >> 2;
    const int mt = blockIdx.y & 3;
    const int n0 = blockIdx.x * GBN;       // 0..3071

    const int lr = tid >> 2;
    const int lc = (tid & 3) * 4;

    const int cnt = gActCount[b];
    if (tid < GBM) {
        const int ic = mt * GBM + tid;
        const bool lv = (ic < cnt);
        slive[tid] = lv;
        sidx[tid]  = lv ? gActIdx[b * TOP_K + ic] : gActIdx[b * TOP_K];
    }
    __syncthreads();

    const float* aptr = A + ((size_t)(b * Nn + sidx[lr])) * DIM + lc;

    float acc[4][4];
#pragma unroll
    for (int i = 0; i < 4; i++)
#pragma unroll
        for (int j = 0; j < 4; j++) acc[i][j] = 0.f;

    for (int k0 = 0; k0 < DIM; k0 += GBK) {
        float4 av = *(const float4*)(aptr + k0);
        float4 bv = *(const float4*)(Wqkv + (size_t)(n0 + lr) * DIM + k0 + lc);
        As[lc + 0][lr] = av.x; As[lc + 1][lr] = av.y;
        As[lc + 2][lr] = av.z; As[lc + 3][lr] = av.w;
        Bs[lc + 0][lr] = bv.x; Bs[lc + 1][lr] = bv.y;
        Bs[lc + 2][lr] = bv.z; Bs[lc + 3][lr] = bv.w;
        __syncthreads();
#pragma unroll
        for (int kk = 0; kk < GBK; kk++) {
            float4 a = *(const float4*)&As[kk][ty * 4];
            float4 bb = *(const float4*)&Bs[kk][tx * 4];
            float ar[4] = {a.x, a.y, a.z, a.w};
            float br[4] = {bb.x, bb.y, bb.z, bb.w};
#pragma unroll
            for (int i = 0; i < 4; i++)
#pragma unroll
                for (int j = 0; j < 4; j++) acc[i][j] += ar[i] * br[j];
        }
        __syncthreads();
    }

#pragma unroll
    for (int i = 0; i < 4; i++) {
        const int r = ty * 4 + i;
        if (slive[r]) {
            const int ic = mt * GBM + r;
#pragma unroll
            for (int j = 0; j < 4; j++) {
                const int n = n0 + tx * 4 + j;
                const int which = n >> 10;          // 0=q, 1=k, 2=v
                const int inner = n & 1023;
                const int h = inner >> 6, d = inner & 63;
                float* dst = (which == 0) ? gQc : (which == 1) ? gKc : gVc;
                dst[(((size_t)(b * HEADS + h)) * TOP_K + ic) * DH + d] = acc[i][j];
            }
        }
    }
}

// ---------------- Kernel 4a: partial x sums (over 128-row slabs) ------------
__global__ __launch_bounds__(256)
void xsum_part_kernel(const float* __restrict__ x)
{
    const int k = blockIdx.x * 256 + threadIdx.x;
    const int b = blockIdx.y;
    const int sl = blockIdx.z;              // 0..7
    float s = 0.f;
    const float* p = x + ((size_t)b * Nn + sl * 128) * DIM + k;
#pragma unroll 8
    for (int n = 0; n < 128; n++) s += p[(size_t)n * DIM];
    gXsumP[((size_t)sl * Bx + b) * DIM + k] = s;
}

__global__ __launch_bounds__(256)
void xsum_reduce_kernel()
{
    const int k = blockIdx.x * 256 + threadIdx.x;
    const int b = blockIdx.y;
    float s = 0.f;
#pragma unroll
    for (int sl = 0; sl < 8; sl++) s += gXsumP[((size_t)sl * Bx + b) * DIM + k];
    gXsum[b * DIM + k] = s;
}

// ---------------- Kernel 4b: VsumAll = Wv . xsum ----------------------------
// block per hd (1024 blocks), 128 threads; computes all 4 batches.
__global__ __launch_bounds__(128)
void vsumall_kernel(const float* __restrict__ Wqkv)
{
    const int hd = blockIdx.x;              // 0..1023
    const int tid = threadIdx.x;
    const float4* wrow = (const float4*)(Wqkv + (size_t)(2 * INNER + hd) * DIM);

    float acc[Bx] = {0.f, 0.f, 0.f, 0.f};
    for (int c = tid; c < DIM / 4; c += 128) {
        float4 w = wrow[c];
#pragma unroll
        for (int b = 0; b < Bx; b++) {
            float4 v = ((const float4*)(gXsum + b * DIM))[c];
            acc[b] += w.x * v.x + w.y * v.y + w.z * v.z + w.w * v.w;
        }
    }
    __shared__ float red[Bx][128];
#pragma unroll
    for (int b = 0; b < Bx; b++) red[b][tid] = acc[b];
    __syncthreads();
    for (int off = 64; off > 0; off >>= 1) {
        if (tid < off)
#pragma unroll
            for (int b = 0; b < Bx; b++) red[b][tid] += red[b][tid + off];
        __syncthreads();
    }
    if (tid < Bx) gVsumAll[tid * 1024 + hd] = red[tid][0];   // [b*1024 + h*64+d]
}

// ---------------- Kernel 4c: VsumIn = VsumAll - sum(active Vc) --------------
__global__ __launch_bounds__(256)
void vsumin_kernel()
{
    const int bh = blockIdx.x;
    const int b = bh >> 4;
    const int tid = threadIdx.x;
    const int jg = tid >> 6;                // 0..3
    const int d  = tid & 63;
    const int cnt = gActCount[b];

    float s = 0.f;
    for (int jc = jg; jc < cnt; jc += 4)
        s += gVc[((size_t)bh * TOP_K + jc) * DH + d];
    __shared__ float red[4][64];
    red[jg][d] = s;
    __syncthreads();
    if (jg == 0)
        gVsumIn[bh * DH + d] = gVsumAll[bh * DH + d]
                             - (red[0][d] + red[1][d] + red[2][d] + red[3][d]);
}

// ---------------- Kernel 5: attention for ACTIVE queries --------------------
#define AT_BJ 64

__global__ __launch_bounds__(128)
void attn_active_kernel()
{
    const int blk = blockIdx.x;
    const int bh = blk >> 1;
    const int half = blk & 1;
    const int b = bh >> 4;
    const int h = bh & 15;
    const int tid = threadIdx.x;
    const int ic = half * 128 + tid;

    const int cnt = gActCount[b];
    const bool live = (ic < cnt);
    const int i = live ? gActIdx[b * TOP_K + ic] : 0;

    __shared__ float4 ksm[AT_BJ][16];
    __shared__ float4 vsm[AT_BJ][16];
    __shared__ float  gsm[AT_BJ];

    float4 q[16];
    {
        const float4* qp = (const float4*)(gQc + ((size_t)bh * TOP_K + ic) * DH);
#pragma unroll
        for (int c = 0; c < 16; c++) q[c] = live ? qp[c] : make_float4(0.f, 0.f, 0.f, 0.f);
    }
    const float gi = live ? gGateC[b * TOP_K + ic] * SCALE : 0.f;

    float4 acc[16];
    {
        const float4* vin = (const float4*)(gVsumIn + bh * DH);
#pragma unroll
        for (int c = 0; c < 16; c++) acc[c] = vin[c];
    }
    float l = (float)(Nn - cnt);

    for (int j0 = 0; j0 < cnt; j0 += AT_BJ) {
        const int jn = min(AT_BJ, cnt - j0);
        __syncthreads();
        for (int t = tid; t < AT_BJ * 16; t += 128) {
            int j = t >> 4, c = t & 15;
            if (j < jn) {
                const size_t src = ((size_t)bh * TOP_K + j0 + j) * 16 + c;
                ksm[j][c] = ((const float4*)gKc)[src];
                vsm[j][c] = ((const float4*)gVc)[src];
            }
        }
        if (tid < AT_BJ && tid < jn) gsm[tid] = gGateC[b * TOP_K + j0 + tid];
        __syncthreads();

        for (int j = 0; j < jn; j++) {
            float s = 0.f;
#pragma unroll
            for (int c = 0; c < 16; c++) {
                float4 kv = ksm[j][c];
                s += q[c].x * kv.x + q[c].y * kv.y + q[c].z * kv.z + q[c].w * kv.w;
            }
            float p = __expf(s * gi * gsm[j]);
            l += p;
#pragma unroll
            for (int c = 0; c < 16; c++) {
                float4 vv = vsm[j][c];
                acc[c].x += p * vv.x; acc[c].y += p * vv.y;
                acc[c].z += p * vv.z; acc[c].w += p * vv.w;
            }
        }
    }

    if (live) {
        const float inv = 1.0f / l;
        float4* orow = (float4*)(gAttnOut + (((size_t)(b * Nn + i)) * HEADS + h) * DH);
#pragma unroll
        for (int c = 0; c < 16; c++) {
            float4 a = acc[c];
            a.x *= inv; a.y *= inv; a.z *= inv; a.w *= inv;
            orow[c] = a;
        }
    }
}

// ---------------- Kernel 6a: output projection for ACTIVE rows --------------
__global__ __launch_bounds__(256)
void out_gemm_active_kernel(const float* __restrict__ Bm, const float* __restrict__ bias,
                            float* __restrict__ C)
{
    __shared__ float As[GBK][GBM + 4];
    __shared__ float Bs[GBK][GBN + 4];
    __shared__ int   sidx[GBM];
    __shared__ int   slive[GBM];

    const int tid = threadIdx.x;
    const int ty = tid >> 4;
    const int tx = tid & 15;
    const int b  = blockIdx.y >> 2;
    const int mt = blockIdx.y & 3;
    const int n0 = blockIdx.x * GBN;

    const int lr = tid >> 2;
    const int lc = (tid & 3) * 4;

    const int cnt = gActCount[b];
    if (tid < GBM) {
        const int ic = mt * GBM + tid;
        const bool lv = (ic < cnt);
        slive[tid] = lv;
        sidx[tid]  = lv ? gActIdx[b * TOP_K + ic] : gActIdx[b * TOP_K];
    }
    __syncthreads();

    const float* aptr = gAttnOut + ((size_t)(b * Nn + sidx[lr])) * INNER + lc;

    float acc[4][4];
#pragma unroll
    for (int i = 0; i < 4; i++)
#pragma unroll
        for (int j = 0; j < 4; j++) acc[i][j] = 0.f;

    for (int k0 = 0; k0 < INNER; k0 += GBK) {
        float4 av = *(const float4*)(aptr + k0);
        float4 bv = *(const float4*)(Bm + (size_t)(n0 + lr) * INNER + k0 + lc);
        As[lc + 0][lr] = av.x; As[lc + 1][lr] = av.y;
        As[lc + 2][lr] = av.z; As[lc + 3][lr] = av.w;
        Bs[lc + 0][lr] = bv.x; Bs[lc + 1][lr] = bv.y;
        Bs[lc + 2][lr] = bv.z; Bs[lc + 3][lr] = bv.w;
        __syncthreads();
#pragma unroll
        for (int kk = 0; kk < GBK; kk++) {
            float4 a = *(const float4*)&As[kk][ty * 4];
            float4 bb = *(const float4*)&Bs[kk][tx * 4];
            float ar[4] = {a.x, a.y, a.z, a.w};
            float br[4] = {bb.x, bb.y, bb.z, bb.w};
#pragma unroll
            for (int i = 0; i < 4; i++)
#pragma unroll
                for (int j = 0; j < 4; j++) acc[i][j] += ar[i] * br[j];
        }
        __syncthreads();
    }

#pragma unroll
    for (int i = 0; i < 4; i++) {
        const int r = ty * 4 + i;
        if (slive[r]) {
            const int token = sidx[r];
#pragma unroll
            for (int j = 0; j < 4; j++) {
                const int n = n0 + tx * 4 + j;
                C[((size_t)(b * Nn + token)) * DIM + n] = acc[i][j] + bias[n];
            }
        }
    }
}

// ---------------- Kernel 6b: shared out-row per batch -----------------------
__global__ __launch_bounds__(256)
void inact_row_kernel(const float* __restrict__ Bm, const float* __restrict__ bias)
{
    const int b = blockIdx.y;
    const int n = blockIdx.x * 256 + threadIdx.x;
    const float invN = 1.0f / (float)Nn;

    const float4* vrow = (const float4*)(gVsumAll + b * INNER);
    const float4* wrow = (const float4*)(Bm + (size_t)n * INNER);
    float s = 0.f;
#pragma unroll 8
    for (int c = 0; c < INNER / 4; c++) {
        float4 v = vrow[c];
        float4 w = wrow[c];
        s += v.x * w.x + v.y * w.y + v.z * w.z + v.w * w.w;
    }
    gInactRow[b * DIM + n] = s * invN + bias[n];
}

// ---------------- Kernel 6c: broadcast shared row to inactive tokens --------
__global__ __launch_bounds__(256)
void inact_bcast_kernel(float* __restrict__ C)
{
    const int token = blockIdx.x;
    if (gGate[token] != 0.0f) return;
    const int b = token >> 10;
    const float4* src = (const float4*)(gInactRow + b * DIM);
    float4* dst = (float4*)(C + (size_t)token * DIM);
    for (int c = threadIdx.x; c < DIM / 4; c += 256) dst[c] = src[c];
}

// ---------------- launch ----------------------------------------------------
extern "C" void kernel_launch(void* const* d_in, const int* in_sizes, int n_in,
                              void* d_out, int out_size)
{
    const float* x     = (const float*)d_in[0];
    const float* w_qkv = (const float*)d_in[1];
    const float* w_out = (const float*)d_in[2];
    const float* b_out = (const float*)d_in[3];
    const float* ln_g  = (const float*)d_in[4];
    const float* ln_b  = (const float*)d_in[5];
    const float* w1    = (const float*)d_in[6];
    const float* b1    = (const float*)d_in[7];
    const float* w2    = (const float*)d_in[8];
    const float* b2    = (const float*)d_in[9];
    float* out = (float*)d_out;

    // gate-first
    wqmean_kernel<<<DH * DIM / 256, 256>>>(w_qkv);
    qmean_gemm_kernel<<<dim3(1, M_TOK / GBM), 256>>>(x);
    gate_scores_kernel<<<M_TOK, 64>>>(ln_g, ln_b, w1, b1, w2, b2);
    topk_gate_kernel<<<Bx, 512>>>();

    // V sums via linearity (independent of active set until vsumin)
    xsum_part_kernel<<<dim3(DIM / 256, Bx, 8), 256>>>(x);
    xsum_reduce_kernel<<<dim3(DIM / 256, Bx), 256>>>();
    vsumall_kernel<<<DIM, 128>>>(w_qkv);

    // active-token QKV projection straight into compact layout
    qkv_active_gemm_kernel<<<dim3(3 * INNER / GBN, Bx * 4), 256>>>(x, w_qkv);
    vsumin_kernel<<<BH, 256>>>();

    // attention + output
    attn_active_kernel<<<BH * 2, 128>>>();
    out_gemm_active_kernel<<<dim3(DIM / GBN, Bx * 4), 256>>>(w_out, b_out, out);
    inact_row_kernel<<<dim3(DIM / 256, Bx), 256>>>(w_out, b_out);
    inact_bcast_kernel<<<M_TOK, 256>>>(out);
}

// round 10
// speedup vs baseline: 5.4279x; 1.1003x over previous
#include <cuda_runtime.h>
#include <cuda_bf16.h>
#include <cstdint>

// Problem constants
#define Bx     4
#define Nn     1024
#define DIM    1024
#define HEADS  16
#define DH     64
#define INNER  1024
#define PROJ_H 16
#define TOP_K  256
#define SCALE  0.125f
#define LN_EPS 1e-5f

#define M_TOK  (Bx * Nn)          // 4096 tokens
#define BH     (Bx * HEADS)       // 64

// ---------------- scratch (device globals; no allocation allowed) -----------
__device__ float gWqm[DH * DIM];                 // (1/16) sum_h w_q rows
__device__ float gQmean[M_TOK * DH];
__device__ float gScores[Bx * Nn];
__device__ float gGate[Bx * Nn];
__device__ float gAttnOut[Bx * Nn * INNER];      // active rows only

__device__ int   gActIdx[Bx * TOP_K];
__device__ int   gActCount[Bx];
__device__ float gGateC[Bx * TOP_K];
__device__ float gQc[BH * TOP_K * DH];           // compact Q (active only)
__device__ float gKc[BH * TOP_K * DH];           // compact K
__device__ float gVc[BH * TOP_K * DH];           // compact V
__device__ float gXsumP[8 * Bx * DIM];           // partial x sums
__device__ float gXsum[Bx * DIM];                // per-batch sum of x rows
__device__ float gVsumAll[BH * DH];              // = Wv . xsum
__device__ float gVsumIn[BH * DH];               // = VsumAll - sum(active V)
__device__ float gInactRow[Bx * DIM];

#define GBM 64
#define GBN 64
#define GBK 16

// ---------------- Kernel 0: fold head-mean into q weights -------------------
__global__ __launch_bounds__(256)
void wqmean_kernel(const float* __restrict__ Wqkv)
{
    const int idx = blockIdx.x * 256 + threadIdx.x;
    const int d = idx >> 10, k = idx & 1023;
    float s = 0.f;
#pragma unroll
    for (int h = 0; h < HEADS; h++)
        s += Wqkv[(size_t)(h * DH + d) * DIM + k];
    gWqm[(size_t)d * DIM + k] = s * (1.0f / 16.0f);
}

// ---------------- Kernel 0b: qmean GEMM (M=4096, N=64, K=1024) --------------
__global__ __launch_bounds__(256)
void qmean_gemm_kernel(const float* __restrict__ A)
{
    __shared__ float As[GBK][GBM + 4];
    __shared__ float Bs[GBK][GBN + 4];

    const int tid = threadIdx.x;
    const int ty = tid >> 4;
    const int tx = tid & 15;
    const int m0 = blockIdx.y * GBM;

    const int lr = tid >> 2;
    const int lc = (tid & 3) * 4;

    float acc[4][4];
#pragma unroll
    for (int i = 0; i < 4; i++)
#pragma unroll
        for (int j = 0; j < 4; j++) acc[i][j] = 0.f;

    for (int k0 = 0; k0 < DIM; k0 += GBK) {
        float4 av = *(const float4*)(A + (size_t)(m0 + lr) * DIM + k0 + lc);
        float4 bv = *(const float4*)(gWqm + (size_t)lr * DIM + k0 + lc);
        As[lc + 0][lr] = av.x; As[lc + 1][lr] = av.y;
        As[lc + 2][lr] = av.z; As[lc + 3][lr] = av.w;
        Bs[lc + 0][lr] = bv.x; Bs[lc + 1][lr] = bv.y;
        Bs[lc + 2][lr] = bv.z; Bs[lc + 3][lr] = bv.w;
        __syncthreads();
#pragma unroll
        for (int kk = 0; kk < GBK; kk++) {
            float4 a = *(const float4*)&As[kk][ty * 4];
            float4 b = *(const float4*)&Bs[kk][tx * 4];
            float ar[4] = {a.x, a.y, a.z, a.w};
            float br[4] = {b.x, b.y, b.z, b.w};
#pragma unroll
            for (int i = 0; i < 4; i++)
#pragma unroll
                for (int j = 0; j < 4; j++) acc[i][j] += ar[i] * br[j];
        }
        __syncthreads();
    }

#pragma unroll
    for (int i = 0; i < 4; i++) {
        const int m = m0 + ty * 4 + i;
#pragma unroll
        for (int j = 0; j < 4; j++)
            gQmean[(size_t)m * DH + tx * 4 + j] = acc[i][j];
    }
}

// ---------------- Kernel 1: gate scores -------------------------------------
__global__ __launch_bounds__(64)
void gate_scores_kernel(const float* __restrict__ ln_g, const float* __restrict__ ln_b,
                        const float* __restrict__ w1, const float* __restrict__ b1,
                        const float* __restrict__ w2, const float* __restrict__ b2)
{
    const int token = blockIdx.x;
    const int d = threadIdx.x;
    const float qm = gQmean[(size_t)token * DH + d];

    __shared__ float sh1[64], sh2[64], Hs[64], hp[16];
    sh1[d] = qm; sh2[d] = qm * qm;
    __syncthreads();
    for (int off = 32; off > 0; off >>= 1) {
        if (d < off) { sh1[d] += sh1[d + off]; sh2[d] += sh2[d + off]; }
        __syncthreads();
    }
    const float mu  = sh1[0] * (1.0f / 64.0f);
    const float var = sh2[0] * (1.0f / 64.0f) - mu * mu;
    const float Hd  = (qm - mu) * rsqrtf(var + LN_EPS) * ln_g[d] + ln_b[d];
    Hs[d] = Hd;
    __syncthreads();

    if (d < PROJ_H) {
        float a = b1[d];
#pragma unroll
        for (int e = 0; e < DH; e++) a += Hs[e] * w1[d * DH + e];
        hp[d] = 0.5f * a * (1.0f + erff(a * 0.70710678118654752f));
    }
    __syncthreads();
    if (d == 0) {
        float sc = b2[0];
#pragma unroll
        for (int p = 0; p < PROJ_H; p++) sc += hp[p] * w2[p];
        gScores[token] = sc;
    }
}

// ---------------- Kernel 2: top-k threshold + sigmoid gate + active list ----
__global__ __launch_bounds__(512)
void topk_gate_kernel()
{
    const int b = blockIdx.x;
    const int tid = threadIdx.x;
    __shared__ float s[Nn];
    __shared__ int cnt;
    for (int t = tid; t < Nn; t += 512) s[t] = gScores[b * Nn + t];
    if (tid == 0) cnt = 0;
    __syncthreads();

    for (int k = 2; k <= Nn; k <<= 1) {
        for (int j = k >> 1; j > 0; j >>= 1) {
            for (int t = tid; t < Nn; t += 512) {
                int ixj = t ^ j;
                if (ixj > t) {
                    float a = s[t], c = s[ixj];
                    bool asc = ((t & k) == 0);
                    if (asc ? (a > c) : (a < c)) { s[t] = c; s[ixj] = a; }
                }
            }
            __syncthreads();
        }
    }
    const float thresh = s[Nn - TOP_K];
    for (int t = tid; t < Nn; t += 512) {
        float sc = gScores[b * Nn + t];
        float g = 0.0f;
        if (sc >= thresh) {
            int pos = atomicAdd(&cnt, 1);
            if (pos < TOP_K) {
                g = 1.0f / (1.0f + expf(-sc));
                gActIdx[b * TOP_K + pos] = t;
                gGateC[b * TOP_K + pos] = g;
            }
        }
        gGate[b * Nn + t] = g;
    }
    __syncthreads();
    if (tid == 0) gActCount[b] = (cnt < TOP_K) ? cnt : TOP_K;
}

// ---------------- Kernel 3: QKV projection for ACTIVE tokens ----------------
// 128x64 tile, 8x4 per thread (FMA-bound). M rows gathered via gActIdx.
// N=3072 (q,k,v); writes compact gQc/gKc/gVc.
__global__ __launch_bounds__(256)
void qkv_active_gemm_kernel(const float* __restrict__ A, const float* __restrict__ Wqkv)
{
    __shared__ float As[GBK][128 + 4];
    __shared__ float Bs[GBK][64 + 4];
    __shared__ int   sidx[128];
    __shared__ int   slive[128];

    const int tid = threadIdx.x;
    const int ty = tid >> 4;               // 0..15 -> 8 rows each
    const int tx = tid & 15;               // 0..15 -> 4 cols each
    const int b  = blockIdx.y >> 1;
    const int mt = blockIdx.y & 1;         // 128-row tile (2 per batch)
    const int n0 = blockIdx.x * 64;        // 0..3071

    const int alr = tid >> 1;              // 0..127
    const int alc = (tid & 1) * 8;         // 0 or 8
    const int blr = tid >> 2;              // 0..63
    const int blc = (tid & 3) * 4;         // 0,4,8,12

    const int cnt = gActCount[b];
    if (tid < 128) {
        const int ic = mt * 128 + tid;
        const bool lv = (ic < cnt);
        slive[tid] = lv;
        sidx[tid]  = lv ? gActIdx[b * TOP_K + ic] : gActIdx[b * TOP_K];
    }
    __syncthreads();

    const float* aptr = A + ((size_t)(b * Nn + sidx[alr])) * DIM + alc;
    const float* bptr = Wqkv + (size_t)(n0 + blr) * DIM + blc;

    float acc[8][4];
#pragma unroll
    for (int i = 0; i < 8; i++)
#pragma unroll
        for (int j = 0; j < 4; j++) acc[i][j] = 0.f;

    for (int k0 = 0; k0 < DIM; k0 += GBK) {
        float4 a0 = *(const float4*)(aptr + k0);
        float4 a1 = *(const float4*)(aptr + k0 + 4);
        float4 bv = *(const float4*)(bptr + k0);
#pragma unroll
        for (int i = 0; i < 4; i++) {
            As[alc + i][alr]     = ((const float*)&a0)[i];
            As[alc + 4 + i][alr] = ((const float*)&a1)[i];
            Bs[blc + i][blr]     = ((const float*)&bv)[i];
        }
        __syncthreads();
#pragma unroll
        for (int kk = 0; kk < GBK; kk++) {
            float4 x0 = *(const float4*)&As[kk][ty * 8];
            float4 x1 = *(const float4*)&As[kk][ty * 8 + 4];
            float4 y  = *(const float4*)&Bs[kk][tx * 4];
            float xr[8] = {x0.x, x0.y, x0.z, x0.w, x1.x, x1.y, x1.z, x1.w};
            float yr[4] = {y.x, y.y, y.z, y.w};
#pragma unroll
            for (int i = 0; i < 8; i++)
#pragma unroll
                for (int j = 0; j < 4; j++) acc[i][j] += xr[i] * yr[j];
        }
        __syncthreads();
    }

#pragma unroll
    for (int i = 0; i < 8; i++) {
        const int r = ty * 8 + i;
        if (slive[r]) {
            const int ic = mt * 128 + r;
#pragma unroll
            for (int j = 0; j < 4; j++) {
                const int n = n0 + tx * 4 + j;
                const int which = n >> 10;          // 0=q, 1=k, 2=v
                const int inner = n & 1023;
                const int h = inner >> 6, d = inner & 63;
                float* dst = (which == 0) ? gQc : (which == 1) ? gKc : gVc;
                dst[(((size_t)(b * HEADS + h)) * TOP_K + ic) * DH + d] = acc[i][j];
            }
        }
    }
}

// ---------------- Kernel 4a: partial x sums ---------------------------------
__global__ __launch_bounds__(256)
void xsum_part_kernel(const float* __restrict__ x)
{
    const int k = blockIdx.x * 256 + threadIdx.x;
    const int b = blockIdx.y;
    const int sl = blockIdx.z;
    float s = 0.f;
    const float* p = x + ((size_t)b * Nn + sl * 128) * DIM + k;
#pragma unroll 8
    for (int n = 0; n < 128; n++) s += p[(size_t)n * DIM];
    gXsumP[((size_t)sl * Bx + b) * DIM + k] = s;
}

__global__ __launch_bounds__(256)
void xsum_reduce_kernel()
{
    const int k = blockIdx.x * 256 + threadIdx.x;
    const int b = blockIdx.y;
    float s = 0.f;
#pragma unroll
    for (int sl = 0; sl < 8; sl++) s += gXsumP[((size_t)sl * Bx + b) * DIM + k];
    gXsum[b * DIM + k] = s;
}

// ---------------- Kernel 4b: VsumAll = Wv . xsum ----------------------------
__global__ __launch_bounds__(128)
void vsumall_kernel(const float* __restrict__ Wqkv)
{
    const int hd = blockIdx.x;
    const int tid = threadIdx.x;
    const float4* wrow = (const float4*)(Wqkv + (size_t)(2 * INNER + hd) * DIM);

    float acc[Bx] = {0.f, 0.f, 0.f, 0.f};
    for (int c = tid; c < DIM / 4; c += 128) {
        float4 w = wrow[c];
#pragma unroll
        for (int b = 0; b < Bx; b++) {
            float4 v = ((const float4*)(gXsum + b * DIM))[c];
            acc[b] += w.x * v.x + w.y * v.y + w.z * v.z + w.w * v.w;
        }
    }
    __shared__ float red[Bx][128];
#pragma unroll
    for (int b = 0; b < Bx; b++) red[b][tid] = acc[b];
    __syncthreads();
    for (int off = 64; off > 0; off >>= 1) {
        if (tid < off)
#pragma unroll
            for (int b = 0; b < Bx; b++) red[b][tid] += red[b][tid + off];
        __syncthreads();
    }
    if (tid < Bx) gVsumAll[tid * 1024 + hd] = red[tid][0];
}

// ---------------- Kernel 4c: VsumIn = VsumAll - sum(active Vc) --------------
__global__ __launch_bounds__(256)
void vsumin_kernel()
{
    const int bh = blockIdx.x;
    const int b = bh >> 4;
    const int tid = threadIdx.x;
    const int jg = tid >> 6;
    const int d  = tid & 63;
    const int cnt = gActCount[b];

    float s = 0.f;
    for (int jc = jg; jc < cnt; jc += 4)
        s += gVc[((size_t)bh * TOP_K + jc) * DH + d];
    __shared__ float red[4][64];
    red[jg][d] = s;
    __syncthreads();
    if (jg == 0)
        gVsumIn[bh * DH + d] = gVsumAll[bh * DH + d]
                             - (red[0][d] + red[1][d] + red[2][d] + red[3][d]);
}

// ---------------- Kernel 5: attention for ACTIVE queries --------------------
#define AT_BJ 64

__global__ __launch_bounds__(128)
void attn_active_kernel()
{
    const int blk = blockIdx.x;
    const int bh = blk >> 1;
    const int half = blk & 1;
    const int b = bh >> 4;
    const int h = bh & 15;
    const int tid = threadIdx.x;
    const int ic = half * 128 + tid;

    const int cnt = gActCount[b];
    const bool live = (ic < cnt);
    const int i = live ? gActIdx[b * TOP_K + ic] : 0;

    __shared__ float4 ksm[AT_BJ][16];
    __shared__ float4 vsm[AT_BJ][16];
    __shared__ float  gsm[AT_BJ];

    float4 q[16];
    {
        const float4* qp = (const float4*)(gQc + ((size_t)bh * TOP_K + ic) * DH);
#pragma unroll
        for (int c = 0; c < 16; c++) q[c] = live ? qp[c] : make_float4(0.f, 0.f, 0.f, 0.f);
    }
    const float gi = live ? gGateC[b * TOP_K + ic] * SCALE : 0.f;

    float4 acc[16];
    {
        const float4* vin = (const float4*)(gVsumIn + bh * DH);
#pragma unroll
        for (int c = 0; c < 16; c++) acc[c] = vin[c];
    }
    float l = (float)(Nn - cnt);

    for (int j0 = 0; j0 < cnt; j0 += AT_BJ) {
        const int jn = min(AT_BJ, cnt - j0);
        __syncthreads();
        for (int t = tid; t < AT_BJ * 16; t += 128) {
            int j = t >> 4, c = t & 15;
            if (j < jn) {
                const size_t src = ((size_t)bh * TOP_K + j0 + j) * 16 + c;
                ksm[j][c] = ((const float4*)gKc)[src];
                vsm[j][c] = ((const float4*)gVc)[src];
            }
        }
        if (tid < AT_BJ && tid < jn) gsm[tid] = gGateC[b * TOP_K + j0 + tid];
        __syncthreads();

        for (int j = 0; j < jn; j++) {
            float s = 0.f;
#pragma unroll
            for (int c = 0; c < 16; c++) {
                float4 kv = ksm[j][c];
                s += q[c].x * kv.x + q[c].y * kv.y + q[c].z * kv.z + q[c].w * kv.w;
            }
            float p = __expf(s * gi * gsm[j]);
            l += p;
#pragma unroll
            for (int c = 0; c < 16; c++) {
                float4 vv = vsm[j][c];
                acc[c].x += p * vv.x; acc[c].y += p * vv.y;
                acc[c].z += p * vv.z; acc[c].w += p * vv.w;
            }
        }
    }

    if (live) {
        const float inv = 1.0f / l;
        float4* orow = (float4*)(gAttnOut + (((size_t)(b * Nn + i)) * HEADS + h) * DH);
#pragma unroll
        for (int c = 0; c < 16; c++) {
            float4 a = acc[c];
            a.x *= inv; a.y *= inv; a.z *= inv; a.w *= inv;
            orow[c] = a;
        }
    }
}

// ---------------- Kernel 6a: output projection for ACTIVE rows --------------
// 128x64 tile, 8x4 per thread; M gathered via gActIdx; N=1024.
__global__ __launch_bounds__(256)
void out_gemm_active_kernel(const float* __restrict__ Bm, const float* __restrict__ bias,
                            float* __restrict__ C)
{
    __shared__ float As[GBK][128 + 4];
    __shared__ float Bs[GBK][64 + 4];
    __shared__ int   sidx[128];
    __shared__ int   slive[128];

    const int tid = threadIdx.x;
    const int ty = tid >> 4;
    const int tx = tid & 15;
    const int b  = blockIdx.y >> 1;
    const int mt = blockIdx.y & 1;
    const int n0 = blockIdx.x * 64;

    const int alr = tid >> 1;
    const int alc = (tid & 1) * 8;
    const int blr = tid >> 2;
    const int blc = (tid & 3) * 4;

    const int cnt = gActCount[b];
    if (tid < 128) {
        const int ic = mt * 128 + tid;
        const bool lv = (ic < cnt);
        slive[tid] = lv;
        sidx[tid]  = lv ? gActIdx[b * TOP_K + ic] : gActIdx[b * TOP_K];
    }
    __syncthreads();

    const float* aptr = gAttnOut + ((size_t)(b * Nn + sidx[alr])) * INNER + alc;
    const float* bptr = Bm + (size_t)(n0 + blr) * INNER + blc;

    float acc[8][4];
#pragma unroll
    for (int i = 0; i < 8; i++)
#pragma unroll
        for (int j = 0; j < 4; j++) acc[i][j] = 0.f;

    for (int k0 = 0; k0 < INNER; k0 += GBK) {
        float4 a0 = *(const float4*)(aptr + k0);
        float4 a1 = *(const float4*)(aptr + k0 + 4);
        float4 bv = *(const float4*)(bptr + k0);
#pragma unroll
        for (int i = 0; i < 4; i++) {
            As[alc + i][alr]     = ((const float*)&a0)[i];
            As[alc + 4 + i][alr] = ((const float*)&a1)[i];
            Bs[blc + i][blr]     = ((const float*)&bv)[i];
        }
        __syncthreads();
#pragma unroll
        for (int kk = 0; kk < GBK; kk++) {
            float4 x0 = *(const float4*)&As[kk][ty * 8];
            float4 x1 = *(const float4*)&As[kk][ty * 8 + 4];
            float4 y  = *(const float4*)&Bs[kk][tx * 4];
            float xr[8] = {x0.x, x0.y, x0.z, x0.w, x1.x, x1.y, x1.z, x1.w};
            float yr[4] = {y.x, y.y, y.z, y.w};
#pragma unroll
            for (int i = 0; i < 8; i++)
#pragma unroll
                for (int j = 0; j < 4; j++) acc[i][j] += xr[i] * yr[j];
        }
        __syncthreads();
    }

#pragma unroll
    for (int i = 0; i < 8; i++) {
        const int r = ty * 8 + i;
        if (slive[r]) {
            const int token = sidx[r];
#pragma unroll
            for (int j = 0; j < 4; j++) {
                const int n = n0 + tx * 4 + j;
                C[((size_t)(b * Nn + token)) * DIM + n] = acc[i][j] + bias[n];
            }
        }
    }
}

// ---------------- Kernel 6b: shared out-row per batch -----------------------
__global__ __launch_bounds__(256)
void inact_row_kernel(const float* __restrict__ Bm, const float* __restrict__ bias)
{
    const int b = blockIdx.y;
    const int n = blockIdx.x * 256 + threadIdx.x;
    const float invN = 1.0f / (float)Nn;

    const float4* vrow = (const float4*)(gVsumAll + b * INNER);
    const float4* wrow = (const float4*)(Bm + (size_t)n * INNER);
    float s = 0.f;
#pragma unroll 8
    for (int c = 0; c < INNER / 4; c++) {
        float4 v = vrow[c];
        float4 w = wrow[c];
        s += v.x * w.x + v.y * w.y + v.z * w.z + v.w * w.w;
    }
    gInactRow[b * DIM + n] = s * invN + bias[n];
}

// ---------------- Kernel 6c: broadcast shared row to inactive tokens --------
__global__ __launch_bounds__(256)
void inact_bcast_kernel(float* __restrict__ C)
{
    const int token = blockIdx.x;
    if (gGate[token] != 0.0f) return;
    const int b = token >> 10;
    const float4* src = (const float4*)(gInactRow + b * DIM);
    float4* dst = (float4*)(C + (size_t)token * DIM);
    for (int c = threadIdx.x; c < DIM / 4; c += 256) dst[c] = src[c];
}

// ---------------- launch ----------------------------------------------------
extern "C" void kernel_launch(void* const* d_in, const int* in_sizes, int n_in,
                              void* d_out, int out_size)
{
    const float* x     = (const float*)d_in[0];
    const float* w_qkv = (const float*)d_in[1];
    const float* w_out = (const float*)d_in[2];
    const float* b_out = (const float*)d_in[3];
    const float* ln_g  = (const float*)d_in[4];
    const float* ln_b  = (const float*)d_in[5];
    const float* w1    = (const float*)d_in[6];
    const float* b1    = (const float*)d_in[7];
    const float* w2    = (const float*)d_in[8];
    const float* b2    = (const float*)d_in[9];
    float* out = (float*)d_out;

    // gate-first
    wqmean_kernel<<<DH * DIM / 256, 256>>>(w_qkv);
    qmean_gemm_kernel<<<dim3(1, M_TOK / GBM), 256>>>(x);
    gate_scores_kernel<<<M_TOK, 64>>>(ln_g, ln_b, w1, b1, w2, b2);
    topk_gate_kernel<<<Bx, 512>>>();

    // V sums via linearity
    xsum_part_kernel<<<dim3(DIM / 256, Bx, 8), 256>>>(x);
    xsum_reduce_kernel<<<dim3(DIM / 256, Bx), 256>>>();
    vsumall_kernel<<<DIM, 128>>>(w_qkv);

    // active-token QKV projection straight into compact layout (128x64 tiles)
    qkv_active_gemm_kernel<<<dim3(3 * INNER / 64, Bx * 2), 256>>>(x, w_qkv);
    vsumin_kernel<<<BH, 256>>>();

    // attention + output
    attn_active_kernel<<<BH * 2, 128>>>();
    out_gemm_active_kernel<<<dim3(DIM / 64, Bx * 2), 256>>>(w_out, b_out, out);
    inact_row_kernel<<<dim3(DIM / 256, Bx), 256>>>(w_out, b_out);
    inact_bcast_kernel<<<M_TOK, 256>>>(out);
}